// round 1
// baseline (speedup 1.0000x reference)
#include <cuda_runtime.h>
#include <math.h>

#define B_  4
#define S_  2048
#define D_  1024
#define H_  16
#define DK_ 64
#define DV_ 64

// Scratch (alloc-free rule: __device__ globals)
__device__ float g_q[B_*H_*S_*DK_];   // [B,H,S,DK]
__device__ float g_k[B_*H_*S_*DK_];   // [B,H,S,DK]
__device__ float g_v[B_*H_*S_*DV_];   // [B,H,S,DV]
__device__ float g_a[B_*S_*H_*DV_];   // [B,S,H*DV]

// ---------------------------------------------------------------------------
// Tiled fp32 GEMM: C[M,N] = A[M,K] @ W[K,N] + bias
// 128x128 tile, K-step 8, 256 threads, 8x8 microtile.
// MODE 0: scatter-store into [B,H,S,64] layout (r=b*S+s, c=h*64+dk)
// MODE 1: plain row-major store
// ---------------------------------------------------------------------------
template<int MODE>
__global__ __launch_bounds__(256)
void gemm_k(const float* __restrict__ A, const float* __restrict__ W,
            const float* __restrict__ bias, float* __restrict__ C,
            int M, int N, int K)
{
    __shared__ float As[8][128];
    __shared__ float Bs[8][132];

    const int tx = threadIdx.x, ty = threadIdx.y;   // 16 x 16
    const int tid = ty * 16 + tx;
    const int cBase = blockIdx.x * 128;
    const int rBase = blockIdx.y * 128;

    const int arow = tid >> 1;            // 0..127
    const int aseg = (tid & 1) * 4;       // 0 or 4
    const int brow = tid >> 5;            // 0..7
    const int bcol = (tid & 31) * 4;      // 0..124

    float acc[8][8];
#pragma unroll
    for (int i = 0; i < 8; i++)
#pragma unroll
        for (int j = 0; j < 8; j++) acc[i][j] = 0.f;

    for (int k0 = 0; k0 < K; k0 += 8) {
        float4 av = *(const float4*)(A + (size_t)(rBase + arow) * K + k0 + aseg);
        As[aseg + 0][arow] = av.x;
        As[aseg + 1][arow] = av.y;
        As[aseg + 2][arow] = av.z;
        As[aseg + 3][arow] = av.w;
        float4 bv = *(const float4*)(W + (size_t)(k0 + brow) * N + cBase + bcol);
        *(float4*)&Bs[brow][bcol] = bv;
        __syncthreads();

#pragma unroll
        for (int kk = 0; kk < 8; kk++) {
            float a[8], b[8];
#pragma unroll
            for (int i = 0; i < 4; i++) {
                a[i]     = As[kk][ty * 4 + i];
                a[4 + i] = As[kk][64 + ty * 4 + i];
            }
#pragma unroll
            for (int j = 0; j < 4; j++) {
                b[j]     = Bs[kk][tx * 4 + j];
                b[4 + j] = Bs[kk][64 + tx * 4 + j];
            }
#pragma unroll
            for (int i = 0; i < 8; i++)
#pragma unroll
                for (int j = 0; j < 8; j++)
                    acc[i][j] = fmaf(a[i], b[j], acc[i][j]);
        }
        __syncthreads();
    }

#pragma unroll
    for (int i = 0; i < 8; i++) {
        int r = rBase + ((i < 4) ? (ty * 4 + i) : (64 + ty * 4 + (i - 4)));
#pragma unroll
        for (int j = 0; j < 8; j++) {
            int c = cBase + ((j < 4) ? (tx * 4 + j) : (64 + tx * 4 + (j - 4)));
            float val = acc[i][j] + bias[c];
            if (MODE == 0) {
                int b  = r >> 11;          // r / 2048
                int s  = r & 2047;
                int h  = c >> 6;
                int dk = c & 63;
                C[(((size_t)(b * H_ + h) * S_) + s) * DK_ + dk] = val;
            } else {
                C[(size_t)r * N + c] = val;
            }
        }
    }
}

// ---------------------------------------------------------------------------
// Flash-style attention, fp32.
// Per block: 64 query rows of one (b,h); loop over 2048 keys in tiles of 32.
// blockDim (8,8) = 64 threads. Scores microtile 8x4, output microtile 8x8.
// Shared < 48KB (static).
// Writes output in [B, S, H*DV] layout for the final GEMM.
// ---------------------------------------------------------------------------
__global__ __launch_bounds__(64)
void attn_k(const float* __restrict__ q, const float* __restrict__ k,
            const float* __restrict__ v, const int* __restrict__ mask,
            float* __restrict__ out)
{
    __shared__ float q_s[64 * 65];   // [64 rows][64 d] stride 65
    __shared__ float k_s[32 * 65];   // [32 keys][64 d]
    __shared__ float v_s[32 * 65];   // [32 keys][64 d]
    __shared__ float p_s[64 * 33];   // [64 rows][32 keys] stride 33
    __shared__ float mn[32];

    const int tx = threadIdx.x, ty = threadIdx.y;  // 8 x 8
    const int tid = ty * 8 + tx;
    const int qb = blockIdx.x * 64;
    const int h  = blockIdx.y;
    const int b  = blockIdx.z;

    const float* qbh = q + ((size_t)(b * H_ + h) * S_) * DK_;
    const float* kbh = k + ((size_t)(b * H_ + h) * S_) * DK_;
    const float* vbh = v + ((size_t)(b * H_ + h) * S_) * DV_;

    // load Q tile: 64x64 floats, 16 float4 per thread
#pragma unroll
    for (int t = 0; t < 16; t++) {
        int idx = tid + t * 64;            // float4 index, 0..1023
        int row = idx >> 4;                // 16 float4 per row
        int c4  = (idx & 15) * 4;
        float4 vv = *(const float4*)(qbh + (size_t)(qb + row) * DK_ + c4);
        q_s[row * 65 + c4 + 0] = vv.x;
        q_s[row * 65 + c4 + 1] = vv.y;
        q_s[row * 65 + c4 + 2] = vv.z;
        q_s[row * 65 + c4 + 3] = vv.w;
    }

    float m[8], l[8], o[8][8];
#pragma unroll
    for (int i = 0; i < 8; i++) {
        m[i] = -1e30f; l[i] = 0.f;
#pragma unroll
        for (int j = 0; j < 8; j++) o[i][j] = 0.f;
    }

    for (int kt = 0; kt < S_ / 32; kt++) {
        const int kBase = kt * 32;
        // load K,V tiles: 32x64 each, 8 float4 per thread per tile
#pragma unroll
        for (int t = 0; t < 8; t++) {
            int idx = tid + t * 64;        // 0..511 float4
            int row = idx >> 4;
            int c4  = (idx & 15) * 4;
            float4 kv = *(const float4*)(kbh + (size_t)(kBase + row) * DK_ + c4);
            k_s[row * 65 + c4 + 0] = kv.x;
            k_s[row * 65 + c4 + 1] = kv.y;
            k_s[row * 65 + c4 + 2] = kv.z;
            k_s[row * 65 + c4 + 3] = kv.w;
            float4 vv = *(const float4*)(vbh + (size_t)(kBase + row) * DV_ + c4);
            v_s[row * 65 + c4 + 0] = vv.x;
            v_s[row * 65 + c4 + 1] = vv.y;
            v_s[row * 65 + c4 + 2] = vv.z;
            v_s[row * 65 + c4 + 3] = vv.w;
        }
        if (tid < 32)
            mn[tid] = -1.0e9f * (float)mask[(size_t)b * S_ + kBase + tid];
        __syncthreads();

        // scores: s[i][j], rows = ty*8+i, key cols = tx*4+j
        float s[8][4];
#pragma unroll
        for (int i = 0; i < 8; i++)
#pragma unroll
            for (int j = 0; j < 4; j++) s[i][j] = 0.f;

#pragma unroll 4
        for (int d = 0; d < 64; d++) {
            float a[8], bb[4];
#pragma unroll
            for (int i = 0; i < 8; i++) a[i] = q_s[(ty * 8 + i) * 65 + d];
#pragma unroll
            for (int j = 0; j < 4; j++) bb[j] = k_s[(tx * 4 + j) * 65 + d];
#pragma unroll
            for (int i = 0; i < 8; i++)
#pragma unroll
                for (int j = 0; j < 4; j++)
                    s[i][j] = fmaf(a[i], bb[j], s[i][j]);
        }
#pragma unroll
        for (int i = 0; i < 8; i++)
#pragma unroll
            for (int j = 0; j < 4; j++)
                s[i][j] = s[i][j] * 0.125f + mn[tx * 4 + j];

        // online softmax per row (row group = 8 lanes, same ty)
#pragma unroll
        for (int i = 0; i < 8; i++) {
            float tm = s[i][0];
#pragma unroll
            for (int j = 1; j < 4; j++) tm = fmaxf(tm, s[i][j]);
            tm = fmaxf(tm, __shfl_xor_sync(0xffffffffu, tm, 4));
            tm = fmaxf(tm, __shfl_xor_sync(0xffffffffu, tm, 2));
            tm = fmaxf(tm, __shfl_xor_sync(0xffffffffu, tm, 1));
            float nm = fmaxf(m[i], tm);
            float corr = __expf(m[i] - nm);
            float rs = 0.f;
#pragma unroll
            for (int j = 0; j < 4; j++) {
                s[i][j] = __expf(s[i][j] - nm);
                rs += s[i][j];
            }
            rs += __shfl_xor_sync(0xffffffffu, rs, 4);
            rs += __shfl_xor_sync(0xffffffffu, rs, 2);
            rs += __shfl_xor_sync(0xffffffffu, rs, 1);
            l[i] = l[i] * corr + rs;
            m[i] = nm;
#pragma unroll
            for (int j = 0; j < 8; j++) o[i][j] *= corr;
#pragma unroll
            for (int j = 0; j < 4; j++)
                p_s[(ty * 8 + i) * 33 + tx * 4 + j] = s[i][j];
        }
        __syncthreads();

        // o += P @ V : output cols = tx*8+dd
#pragma unroll 4
        for (int jj = 0; jj < 32; jj++) {
            float vv[8];
#pragma unroll
            for (int dd = 0; dd < 8; dd++) vv[dd] = v_s[jj * 65 + tx * 8 + dd];
#pragma unroll
            for (int i = 0; i < 8; i++) {
                float pp = p_s[(ty * 8 + i) * 33 + jj];
#pragma unroll
                for (int dd = 0; dd < 8; dd++)
                    o[i][dd] = fmaf(pp, vv[dd], o[i][dd]);
            }
        }
        __syncthreads();
    }

    // finalize: out[b, s, h*DV + d]
#pragma unroll
    for (int i = 0; i < 8; i++) {
        float inv = 1.f / l[i];
        int srow = qb + ty * 8 + i;
        size_t base = ((size_t)(b * S_ + srow) * H_ + h) * DV_ + tx * 8;
#pragma unroll
        for (int dd = 0; dd < 8; dd++)
            out[base + dd] = o[i][dd] * inv;
    }
}

// ---------------------------------------------------------------------------
extern "C" void kernel_launch(void* const* d_in, const int* in_sizes, int n_in,
                              void* d_out, int out_size)
{
    const float* query = (const float*)d_in[0];
    const float* key   = (const float*)d_in[1];
    const float* value = (const float*)d_in[2];
    const int*   amask = (const int*)d_in[3];
    const float* wq = (const float*)d_in[4];
    const float* bq = (const float*)d_in[5];
    const float* wk = (const float*)d_in[6];
    const float* bk = (const float*)d_in[7];
    const float* wv = (const float*)d_in[8];
    const float* bv = (const float*)d_in[9];
    const float* wo = (const float*)d_in[10];
    const float* bo = (const float*)d_in[11];
    float* out = (float*)d_out;

    float *gq, *gk, *gv, *ga;
    cudaGetSymbolAddress((void**)&gq, g_q);
    cudaGetSymbolAddress((void**)&gk, g_k);
    cudaGetSymbolAddress((void**)&gv, g_v);
    cudaGetSymbolAddress((void**)&ga, g_a);

    const int M = B_ * S_;       // 8192
    const int N = H_ * DK_;      // 1024
    const int K = D_;            // 1024

    dim3 gblk(16, 16);
    dim3 ggrid(N / 128, M / 128);

    gemm_k<0><<<ggrid, gblk>>>(query, wq, bq, gq, M, N, K);
    gemm_k<0><<<ggrid, gblk>>>(key,   wk, bk, gk, M, N, K);
    gemm_k<0><<<ggrid, gblk>>>(value, wv, bv, gv, M, N, K);

    dim3 ablk(8, 8);
    dim3 agrid(S_ / 64, H_, B_);
    attn_k<<<agrid, ablk>>>(gq, gk, gv, amask, ga);

    dim3 ogrid((H_ * DV_ == 1024 ? 1024 : H_ * DV_) / 128, M / 128);
    gemm_k<1><<<dim3(1024 / 128, M / 128), gblk>>>(ga, wo, bo, out, M, 1024, H_ * DV_);
}

// round 2
// speedup vs baseline: 1.4715x; 1.4715x over previous
#include <cuda_runtime.h>
#include <math.h>
#include <stdint.h>

#define B_  4
#define S_  2048
#define D_  1024
#define H_  16
#define DK_ 64
#define DV_ 64

// Scratch (alloc-free rule: __device__ globals)
__device__ float g_q[B_*H_*S_*DK_];   // [B,H,S,DK]
__device__ float g_k[B_*H_*S_*DK_];   // [B,H,S,DK]
__device__ float g_v[B_*H_*S_*DV_];   // [B,H,S,DV]
__device__ float g_a[B_*S_*H_*DV_];   // [B,S,H*DV]

__device__ __forceinline__ float to_tf32(float x) {
    float r;
    asm("cvt.rna.tf32.f32 %0, %1;" : "=f"(r) : "f"(x));
    return r;
}

__device__ __forceinline__ void mma_tf32(float& d0, float& d1, float& d2, float& d3,
                                         uint32_t a0, uint32_t a1, uint32_t a2, uint32_t a3,
                                         uint32_t b0, uint32_t b1)
{
    asm volatile(
        "mma.sync.aligned.m16n8k8.row.col.f32.tf32.tf32.f32 "
        "{%0,%1,%2,%3}, {%4,%5,%6,%7}, {%8,%9}, {%0,%1,%2,%3};"
        : "+f"(d0), "+f"(d1), "+f"(d2), "+f"(d3)
        : "r"(a0), "r"(a1), "r"(a2), "r"(a3), "r"(b0), "r"(b1));
}

// ---------------------------------------------------------------------------
// tf32 tensor-core GEMM: C[M,N] = A[M,K] @ W[K,N] + bias
// Block tile 128x128, k-step 16, 256 threads = 8 warps (2x4), warp tile 64x32.
// MODE 0: scatter-store into [B,H,S,64] layout   MODE 1: row-major store
// ---------------------------------------------------------------------------
#define PADG 136
template<int MODE>
__global__ __launch_bounds__(256)
void gemm_tc(const float* __restrict__ A, const float* __restrict__ W,
             const float* __restrict__ bias, float* __restrict__ C,
             int M, int N, int K)
{
    __shared__ float As[16 * PADG];   // [k][row], row-padded
    __shared__ float Bs[16 * PADG];   // [k][col]

    const int tid  = threadIdx.x;
    const int warp = tid >> 5;
    const int lane = tid & 31;
    const int g    = lane >> 2;      // groupID 0..7
    const int tig  = lane & 3;       // thread-in-group 0..3
    const int wr   = warp >> 2;      // 0..1  (64 rows each)
    const int wc   = warp & 3;       // 0..3  (32 cols each)

    const int rBase = blockIdx.y * 128;
    const int cBase = blockIdx.x * 128;

    float acc[4][4][4];
#pragma unroll
    for (int mt = 0; mt < 4; mt++)
#pragma unroll
        for (int nt = 0; nt < 4; nt++)
#pragma unroll
            for (int r = 0; r < 4; r++) acc[mt][nt][r] = 0.f;

    for (int k0 = 0; k0 < K; k0 += 16) {
        // stage A: 128 rows x 16 k, store transposed As[k][row]
#pragma unroll
        for (int j = 0; j < 2; j++) {
            int idx = tid + j * 256;          // 0..511 float4
            int r   = idx >> 2;               // row 0..127
            int q   = idx & 3;                // which float4 in the 16-k row
            float4 av = *(const float4*)(A + (size_t)(rBase + r) * K + k0 + q * 4);
            As[(q * 4 + 0) * PADG + r] = to_tf32(av.x);
            As[(q * 4 + 1) * PADG + r] = to_tf32(av.y);
            As[(q * 4 + 2) * PADG + r] = to_tf32(av.z);
            As[(q * 4 + 3) * PADG + r] = to_tf32(av.w);
        }
        // stage B: 16 k x 128 cols, Bs[k][col]
#pragma unroll
        for (int j = 0; j < 2; j++) {
            int idx = tid + j * 256;          // 0..511 float4
            int kr  = idx >> 5;               // k 0..15
            int c4  = (idx & 31) * 4;         // col 0..124
            float4 bv = *(const float4*)(W + (size_t)(k0 + kr) * N + cBase + c4);
            float4 cv;
            cv.x = to_tf32(bv.x); cv.y = to_tf32(bv.y);
            cv.z = to_tf32(bv.z); cv.w = to_tf32(bv.w);
            *(float4*)&Bs[kr * PADG + c4] = cv;
        }
        __syncthreads();

#pragma unroll
        for (int ks = 0; ks < 2; ks++) {
            const int kb = ks * 8;
            uint32_t a[4][4];
#pragma unroll
            for (int mt = 0; mt < 4; mt++) {
                int row0 = wr * 64 + mt * 16;
                a[mt][0] = __float_as_uint(As[(kb + tig)     * PADG + row0 + g]);
                a[mt][1] = __float_as_uint(As[(kb + tig)     * PADG + row0 + g + 8]);
                a[mt][2] = __float_as_uint(As[(kb + tig + 4) * PADG + row0 + g]);
                a[mt][3] = __float_as_uint(As[(kb + tig + 4) * PADG + row0 + g + 8]);
            }
            uint32_t b[4][2];
#pragma unroll
            for (int nt = 0; nt < 4; nt++) {
                int col0 = wc * 32 + nt * 8;
                b[nt][0] = __float_as_uint(Bs[(kb + tig)     * PADG + col0 + g]);
                b[nt][1] = __float_as_uint(Bs[(kb + tig + 4) * PADG + col0 + g]);
            }
#pragma unroll
            for (int mt = 0; mt < 4; mt++)
#pragma unroll
                for (int nt = 0; nt < 4; nt++)
                    mma_tf32(acc[mt][nt][0], acc[mt][nt][1], acc[mt][nt][2], acc[mt][nt][3],
                             a[mt][0], a[mt][1], a[mt][2], a[mt][3],
                             b[nt][0], b[nt][1]);
        }
        __syncthreads();
    }

    // epilogue
#pragma unroll
    for (int mt = 0; mt < 4; mt++) {
#pragma unroll
        for (int nt = 0; nt < 4; nt++) {
#pragma unroll
            for (int half = 0; half < 2; half++) {
                int r = rBase + wr * 64 + mt * 16 + g + half * 8;
                int c = cBase + wc * 32 + nt * 8 + tig * 2;
                float v0 = acc[mt][nt][half * 2 + 0] + bias[c];
                float v1 = acc[mt][nt][half * 2 + 1] + bias[c + 1];
                if (MODE == 0) {
                    int bb = r >> 11;
                    int s  = r & 2047;
                    int h  = c >> 6;
                    int dk = c & 63;
                    float* dst = &g_q[0]; // placeholder; real base passed via C
                    (void)dst;
                    size_t base = (((size_t)(bb * H_ + h) * S_) + s) * DK_ + dk;
                    C[base]     = v0;
                    C[base + 1] = v1;   // dk and dk+1 stay within same head (dk even, <63)
                } else {
                    C[(size_t)r * N + c]     = v0;
                    C[(size_t)r * N + c + 1] = v1;
                }
            }
        }
    }
}

// ---------------------------------------------------------------------------
// Flash-style attention, fp32, v2: 128 threads (8x16), 4 q-rows per thread.
// Per block: 64 query rows of one (b,h); loop over 2048 keys in tiles of 32.
// ---------------------------------------------------------------------------
__global__ __launch_bounds__(128)
void attn_k(const float* __restrict__ q, const float* __restrict__ k,
            const float* __restrict__ v, const int* __restrict__ mask,
            float* __restrict__ out)
{
    __shared__ float q_s[64 * 65];
    __shared__ float k_s[32 * 65];
    __shared__ float v_s[32 * 65];
    __shared__ float p_s[64 * 33];
    __shared__ float mn[32];

    const int tx = threadIdx.x;       // 0..7
    const int ty = threadIdx.y;       // 0..15
    const int tid = ty * 8 + tx;
    const int qb = blockIdx.x * 64;
    const int h  = blockIdx.y;
    const int b  = blockIdx.z;

    const float* qbh = q + ((size_t)(b * H_ + h) * S_) * DK_;
    const float* kbh = k + ((size_t)(b * H_ + h) * S_) * DK_;
    const float* vbh = v + ((size_t)(b * H_ + h) * S_) * DV_;

    // load Q tile: 64x64 floats = 1024 float4, 8 per thread
#pragma unroll
    for (int t = 0; t < 8; t++) {
        int idx = tid + t * 128;
        int row = idx >> 4;
        int c4  = (idx & 15) * 4;
        float4 vv = *(const float4*)(qbh + (size_t)(qb + row) * DK_ + c4);
        q_s[row * 65 + c4 + 0] = vv.x;
        q_s[row * 65 + c4 + 1] = vv.y;
        q_s[row * 65 + c4 + 2] = vv.z;
        q_s[row * 65 + c4 + 3] = vv.w;
    }

    float m[4], l[4], o[4][8];
#pragma unroll
    for (int i = 0; i < 4; i++) {
        m[i] = -1e30f; l[i] = 0.f;
#pragma unroll
        for (int j = 0; j < 8; j++) o[i][j] = 0.f;
    }

    for (int kt = 0; kt < S_ / 32; kt++) {
        const int kBase = kt * 32;
#pragma unroll
        for (int t = 0; t < 4; t++) {
            int idx = tid + t * 128;       // 0..511 float4
            int row = idx >> 4;
            int c4  = (idx & 15) * 4;
            float4 kv = *(const float4*)(kbh + (size_t)(kBase + row) * DK_ + c4);
            k_s[row * 65 + c4 + 0] = kv.x;
            k_s[row * 65 + c4 + 1] = kv.y;
            k_s[row * 65 + c4 + 2] = kv.z;
            k_s[row * 65 + c4 + 3] = kv.w;
            float4 vv = *(const float4*)(vbh + (size_t)(kBase + row) * DV_ + c4);
            v_s[row * 65 + c4 + 0] = vv.x;
            v_s[row * 65 + c4 + 1] = vv.y;
            v_s[row * 65 + c4 + 2] = vv.z;
            v_s[row * 65 + c4 + 3] = vv.w;
        }
        if (tid < 32)
            mn[tid] = -1.0e9f * (float)mask[(size_t)b * S_ + kBase + tid];
        __syncthreads();

        float s[4][4];
#pragma unroll
        for (int i = 0; i < 4; i++)
#pragma unroll
            for (int j = 0; j < 4; j++) s[i][j] = 0.f;

#pragma unroll 8
        for (int d = 0; d < 64; d++) {
            float a[4], bb[4];
#pragma unroll
            for (int i = 0; i < 4; i++) a[i] = q_s[(ty * 4 + i) * 65 + d];
#pragma unroll
            for (int j = 0; j < 4; j++) bb[j] = k_s[(tx * 4 + j) * 65 + d];
#pragma unroll
            for (int i = 0; i < 4; i++)
#pragma unroll
                for (int j = 0; j < 4; j++)
                    s[i][j] = fmaf(a[i], bb[j], s[i][j]);
        }
#pragma unroll
        for (int i = 0; i < 4; i++)
#pragma unroll
            for (int j = 0; j < 4; j++)
                s[i][j] = s[i][j] * 0.125f + mn[tx * 4 + j];

        // online softmax per row (8 tx lanes per row, consecutive in warp)
#pragma unroll
        for (int i = 0; i < 4; i++) {
            float tm = s[i][0];
#pragma unroll
            for (int j = 1; j < 4; j++) tm = fmaxf(tm, s[i][j]);
            tm = fmaxf(tm, __shfl_xor_sync(0xffffffffu, tm, 4));
            tm = fmaxf(tm, __shfl_xor_sync(0xffffffffu, tm, 2));
            tm = fmaxf(tm, __shfl_xor_sync(0xffffffffu, tm, 1));
            float nm = fmaxf(m[i], tm);
            float corr = __expf(m[i] - nm);
            float rs = 0.f;
#pragma unroll
            for (int j = 0; j < 4; j++) {
                s[i][j] = __expf(s[i][j] - nm);
                rs += s[i][j];
            }
            rs += __shfl_xor_sync(0xffffffffu, rs, 4);
            rs += __shfl_xor_sync(0xffffffffu, rs, 2);
            rs += __shfl_xor_sync(0xffffffffu, rs, 1);
            l[i] = l[i] * corr + rs;
            m[i] = nm;
#pragma unroll
            for (int j = 0; j < 8; j++) o[i][j] *= corr;
#pragma unroll
            for (int j = 0; j < 4; j++)
                p_s[(ty * 4 + i) * 33 + tx * 4 + j] = s[i][j];
        }
        __syncthreads();

        // o += P @ V : output cols = tx*8+dd
#pragma unroll 4
        for (int jj = 0; jj < 32; jj++) {
            float vv[8];
#pragma unroll
            for (int dd = 0; dd < 8; dd++) vv[dd] = v_s[jj * 65 + tx * 8 + dd];
#pragma unroll
            for (int i = 0; i < 4; i++) {
                float pp = p_s[(ty * 4 + i) * 33 + jj];
#pragma unroll
                for (int dd = 0; dd < 8; dd++)
                    o[i][dd] = fmaf(pp, vv[dd], o[i][dd]);
            }
        }
        __syncthreads();
    }

#pragma unroll
    for (int i = 0; i < 4; i++) {
        float inv = 1.f / l[i];
        int srow = qb + ty * 4 + i;
        size_t base = ((size_t)(b * S_ + srow) * H_ + h) * DV_ + tx * 8;
#pragma unroll
        for (int dd = 0; dd < 8; dd++)
            out[base + dd] = o[i][dd] * inv;
    }
}

// ---------------------------------------------------------------------------
extern "C" void kernel_launch(void* const* d_in, const int* in_sizes, int n_in,
                              void* d_out, int out_size)
{
    const float* query = (const float*)d_in[0];
    const float* key   = (const float*)d_in[1];
    const float* value = (const float*)d_in[2];
    const int*   amask = (const int*)d_in[3];
    const float* wq = (const float*)d_in[4];
    const float* bq = (const float*)d_in[5];
    const float* wk = (const float*)d_in[6];
    const float* bk = (const float*)d_in[7];
    const float* wv = (const float*)d_in[8];
    const float* bv = (const float*)d_in[9];
    const float* wo = (const float*)d_in[10];
    const float* bo = (const float*)d_in[11];
    float* out = (float*)d_out;

    float *gq, *gk, *gv, *ga;
    cudaGetSymbolAddress((void**)&gq, g_q);
    cudaGetSymbolAddress((void**)&gk, g_k);
    cudaGetSymbolAddress((void**)&gv, g_v);
    cudaGetSymbolAddress((void**)&ga, g_a);

    const int M = B_ * S_;       // 8192
    const int N = H_ * DK_;      // 1024
    const int K = D_;            // 1024

    dim3 ggrid(N / 128, M / 128);

    gemm_tc<0><<<ggrid, 256>>>(query, wq, bq, gq, M, N, K);
    gemm_tc<0><<<ggrid, 256>>>(key,   wk, bk, gk, M, N, K);
    gemm_tc<0><<<ggrid, 256>>>(value, wv, bv, gv, M, N, K);

    dim3 ablk(8, 16);
    dim3 agrid(S_ / 64, H_, B_);
    attn_k<<<agrid, ablk>>>(gq, gk, gv, amask, ga);

    gemm_tc<1><<<dim3(1024 / 128, M / 128), 256>>>(ga, wo, bo, out, M, 1024, H_ * DV_);
}

// round 3
// speedup vs baseline: 2.6490x; 1.8002x over previous
#include <cuda_runtime.h>
#include <math.h>
#include <stdint.h>

#define B_  4
#define S_  2048
#define D_  1024
#define H_  16
#define DK_ 64
#define DV_ 64

// Scratch (alloc-free rule: __device__ globals)
__device__ float g_q[B_*H_*S_*DK_];   // [B,H,S,DK]
__device__ float g_k[B_*H_*S_*DK_];   // [B,H,S,DK]
__device__ float g_v[B_*H_*S_*DV_];   // [B,H,S,DV]
__device__ float g_a[B_*S_*H_*DV_];   // [B,S,H*DV]

__device__ __forceinline__ float to_tf32(float x) {
    float r;
    asm("cvt.rna.tf32.f32 %0, %1;" : "=f"(r) : "f"(x));
    return r;
}

__device__ __forceinline__ void mma_tf32(float& d0, float& d1, float& d2, float& d3,
                                         uint32_t a0, uint32_t a1, uint32_t a2, uint32_t a3,
                                         uint32_t b0, uint32_t b1)
{
    asm volatile(
        "mma.sync.aligned.m16n8k8.row.col.f32.tf32.tf32.f32 "
        "{%0,%1,%2,%3}, {%4,%5,%6,%7}, {%8,%9}, {%0,%1,%2,%3};"
        : "+f"(d0), "+f"(d1), "+f"(d2), "+f"(d3)
        : "r"(a0), "r"(a1), "r"(a2), "r"(a3), "r"(b0), "r"(b1));
}

// ---------------------------------------------------------------------------
// tf32 tensor-core GEMM: C[M,N] = A[M,K] @ W[K,N] + bias
// Block tile 128x128, k-step 16, 256 threads = 8 warps (2x4), warp tile 64x32.
// MODE 0: scatter-store into [B,H,S,64] layout   MODE 1: row-major store
// ---------------------------------------------------------------------------
#define PADG 136
template<int MODE>
__global__ __launch_bounds__(256)
void gemm_tc(const float* __restrict__ A, const float* __restrict__ W,
             const float* __restrict__ bias, float* __restrict__ C,
             int M, int N, int K)
{
    __shared__ float As[16 * PADG];
    __shared__ float Bs[16 * PADG];

    const int tid  = threadIdx.x;
    const int warp = tid >> 5;
    const int lane = tid & 31;
    const int g    = lane >> 2;
    const int tig  = lane & 3;
    const int wr   = warp >> 2;
    const int wc   = warp & 3;

    const int rBase = blockIdx.y * 128;
    const int cBase = blockIdx.x * 128;

    float acc[4][4][4];
#pragma unroll
    for (int mt = 0; mt < 4; mt++)
#pragma unroll
        for (int nt = 0; nt < 4; nt++)
#pragma unroll
            for (int r = 0; r < 4; r++) acc[mt][nt][r] = 0.f;

    for (int k0 = 0; k0 < K; k0 += 16) {
#pragma unroll
        for (int j = 0; j < 2; j++) {
            int idx = tid + j * 256;
            int r   = idx >> 2;
            int q   = idx & 3;
            float4 av = *(const float4*)(A + (size_t)(rBase + r) * K + k0 + q * 4);
            As[(q * 4 + 0) * PADG + r] = to_tf32(av.x);
            As[(q * 4 + 1) * PADG + r] = to_tf32(av.y);
            As[(q * 4 + 2) * PADG + r] = to_tf32(av.z);
            As[(q * 4 + 3) * PADG + r] = to_tf32(av.w);
        }
#pragma unroll
        for (int j = 0; j < 2; j++) {
            int idx = tid + j * 256;
            int kr  = idx >> 5;
            int c4  = (idx & 31) * 4;
            float4 bv = *(const float4*)(W + (size_t)(k0 + kr) * N + cBase + c4);
            float4 cv;
            cv.x = to_tf32(bv.x); cv.y = to_tf32(bv.y);
            cv.z = to_tf32(bv.z); cv.w = to_tf32(bv.w);
            *(float4*)&Bs[kr * PADG + c4] = cv;
        }
        __syncthreads();

#pragma unroll
        for (int ks = 0; ks < 2; ks++) {
            const int kb = ks * 8;
            uint32_t a[4][4];
#pragma unroll
            for (int mt = 0; mt < 4; mt++) {
                int row0 = wr * 64 + mt * 16;
                a[mt][0] = __float_as_uint(As[(kb + tig)     * PADG + row0 + g]);
                a[mt][1] = __float_as_uint(As[(kb + tig)     * PADG + row0 + g + 8]);
                a[mt][2] = __float_as_uint(As[(kb + tig + 4) * PADG + row0 + g]);
                a[mt][3] = __float_as_uint(As[(kb + tig + 4) * PADG + row0 + g + 8]);
            }
            uint32_t b[4][2];
#pragma unroll
            for (int nt = 0; nt < 4; nt++) {
                int col0 = wc * 32 + nt * 8;
                b[nt][0] = __float_as_uint(Bs[(kb + tig)     * PADG + col0 + g]);
                b[nt][1] = __float_as_uint(Bs[(kb + tig + 4) * PADG + col0 + g]);
            }
#pragma unroll
            for (int mt = 0; mt < 4; mt++)
#pragma unroll
                for (int nt = 0; nt < 4; nt++)
                    mma_tf32(acc[mt][nt][0], acc[mt][nt][1], acc[mt][nt][2], acc[mt][nt][3],
                             a[mt][0], a[mt][1], a[mt][2], a[mt][3],
                             b[nt][0], b[nt][1]);
        }
        __syncthreads();
    }

#pragma unroll
    for (int mt = 0; mt < 4; mt++) {
#pragma unroll
        for (int nt = 0; nt < 4; nt++) {
#pragma unroll
            for (int half = 0; half < 2; half++) {
                int r = rBase + wr * 64 + mt * 16 + g + half * 8;
                int c = cBase + wc * 32 + nt * 8 + tig * 2;
                float v0 = acc[mt][nt][half * 2 + 0] + bias[c];
                float v1 = acc[mt][nt][half * 2 + 1] + bias[c + 1];
                if (MODE == 0) {
                    int bb = r >> 11;
                    int s  = r & 2047;
                    int h  = c >> 6;
                    int dk = c & 63;
                    size_t base = (((size_t)(bb * H_ + h) * S_) + s) * DK_ + dk;
                    C[base]     = v0;
                    C[base + 1] = v1;
                } else {
                    C[(size_t)r * N + c]     = v0;
                    C[(size_t)r * N + c + 1] = v1;
                }
            }
        }
    }
}

// ---------------------------------------------------------------------------
// Tensor-core flash attention (tf32 MMA with error compensation).
// Block: 128 threads / 4 warps. 64 q-rows per block (16 per warp).
// Key loop: 32-key tiles. QK^T: Q split hi/lo (2 MMAs). PV: V split hi/lo.
// Strides: q_s 68, k_s 68, v 72, p 36 (conflict-free fragment access).
// ---------------------------------------------------------------------------
#define KT 32

__global__ __launch_bounds__(128)
void attn_tc(const float* __restrict__ q, const float* __restrict__ k,
             const float* __restrict__ v, const int* __restrict__ mask,
             float* __restrict__ out)
{
    __shared__ float q_s[64 * 68];    // Q staging; later per-warp P (16x36 each)
    __shared__ float k_s[KT * 68];    // K_hi (tf32-rounded)
    __shared__ float vh_s[KT * 72];   // V_hi
    __shared__ float vl_s[KT * 72];   // V_lo
    __shared__ float mn[KT];

    const int tid  = threadIdx.x;
    const int warp = tid >> 5;
    const int lane = tid & 31;
    const int g    = lane >> 2;      // 0..7
    const int tig  = lane & 3;       // 0..3

    const int qb = blockIdx.x * 64;
    const int h  = blockIdx.y;
    const int b  = blockIdx.z;

    const float* qbh = q + ((size_t)(b * H_ + h) * S_) * DK_;
    const float* kbh = k + ((size_t)(b * H_ + h) * S_) * DK_;
    const float* vbh = v + ((size_t)(b * H_ + h) * S_) * DV_;

    // stage Q tile 64x64 (1024 float4, 8 per thread)
#pragma unroll
    for (int t = 0; t < 8; t++) {
        int idx = tid + t * 128;
        int row = idx >> 4;
        int c4  = (idx & 15) * 4;
        float4 vv = *(const float4*)(qbh + (size_t)(qb + row) * DK_ + c4);
        *(float4*)&q_s[row * 68 + c4] = vv;
    }
    __syncthreads();

    // extract Q fragments (hi/lo split), register-resident for whole loop
    uint32_t qhi[8][4], qlo[8][4];
    {
        const int r0 = warp * 16 + g;
        const int r1 = r0 + 8;
#pragma unroll
        for (int kt = 0; kt < 8; kt++) {
            float f0 = q_s[r0 * 68 + kt * 8 + tig];
            float f1 = q_s[r1 * 68 + kt * 8 + tig];
            float f2 = q_s[r0 * 68 + kt * 8 + tig + 4];
            float f3 = q_s[r1 * 68 + kt * 8 + tig + 4];
            float h0 = to_tf32(f0), h1 = to_tf32(f1), h2 = to_tf32(f2), h3 = to_tf32(f3);
            qhi[kt][0] = __float_as_uint(h0);
            qhi[kt][1] = __float_as_uint(h1);
            qhi[kt][2] = __float_as_uint(h2);
            qhi[kt][3] = __float_as_uint(h3);
            qlo[kt][0] = __float_as_uint(to_tf32(f0 - h0));
            qlo[kt][1] = __float_as_uint(to_tf32(f1 - h1));
            qlo[kt][2] = __float_as_uint(to_tf32(f2 - h2));
            qlo[kt][3] = __float_as_uint(to_tf32(f3 - h3));
        }
    }
    __syncthreads();   // all warps done with q_s; region reused as P
    float* p_s = q_s + warp * (16 * 36);

    float m0 = -1e30f, m1 = -1e30f, l0 = 0.f, l1 = 0.f;
    float o[8][4];
#pragma unroll
    for (int nt = 0; nt < 8; nt++)
#pragma unroll
        for (int r = 0; r < 4; r++) o[nt][r] = 0.f;

    for (int kt0 = 0; kt0 < S_; kt0 += KT) {
        // load K tile (rounded to tf32) and V tile (hi/lo split)
#pragma unroll
        for (int t = 0; t < 4; t++) {
            int idx = tid + t * 128;          // 0..511 float4
            int row = idx >> 4;
            int c4  = (idx & 15) * 4;
            float4 kv = *(const float4*)(kbh + (size_t)(kt0 + row) * DK_ + c4);
            float4 kh;
            kh.x = to_tf32(kv.x); kh.y = to_tf32(kv.y);
            kh.z = to_tf32(kv.z); kh.w = to_tf32(kv.w);
            *(float4*)&k_s[row * 68 + c4] = kh;

            float4 vv = *(const float4*)(vbh + (size_t)(kt0 + row) * DV_ + c4);
            float4 vh, vl;
            vh.x = to_tf32(vv.x); vl.x = to_tf32(vv.x - vh.x);
            vh.y = to_tf32(vv.y); vl.y = to_tf32(vv.y - vh.y);
            vh.z = to_tf32(vv.z); vl.z = to_tf32(vv.z - vh.z);
            vh.w = to_tf32(vv.w); vl.w = to_tf32(vv.w - vh.w);
            *(float4*)&vh_s[row * 72 + c4] = vh;
            *(float4*)&vl_s[row * 72 + c4] = vl;
        }
        if (tid < KT)
            mn[tid] = -1.0e9f * (float)mask[(size_t)b * S_ + kt0 + tid];
        __syncthreads();

        // ---- QK^T: scores 16x32 per warp, Q-split (2 MMAs) ----
        float s[4][4];
#pragma unroll
        for (int nt = 0; nt < 4; nt++)
#pragma unroll
            for (int r = 0; r < 4; r++) s[nt][r] = 0.f;

#pragma unroll
        for (int kt = 0; kt < 8; kt++) {
#pragma unroll
            for (int nt = 0; nt < 4; nt++) {
                uint32_t b0 = __float_as_uint(k_s[(nt * 8 + g) * 68 + kt * 8 + tig]);
                uint32_t b1 = __float_as_uint(k_s[(nt * 8 + g) * 68 + kt * 8 + tig + 4]);
                mma_tf32(s[nt][0], s[nt][1], s[nt][2], s[nt][3],
                         qhi[kt][0], qhi[kt][1], qhi[kt][2], qhi[kt][3], b0, b1);
                mma_tf32(s[nt][0], s[nt][1], s[nt][2], s[nt][3],
                         qlo[kt][0], qlo[kt][1], qlo[kt][2], qlo[kt][3], b0, b1);
            }
        }

        // scale + mask
#pragma unroll
        for (int nt = 0; nt < 4; nt++) {
            float ma = mn[nt * 8 + 2 * tig];
            float mb = mn[nt * 8 + 2 * tig + 1];
            s[nt][0] = s[nt][0] * 0.125f + ma;
            s[nt][1] = s[nt][1] * 0.125f + mb;
            s[nt][2] = s[nt][2] * 0.125f + ma;
            s[nt][3] = s[nt][3] * 0.125f + mb;
        }

        // ---- online softmax (rows g and g+8) ----
        float tm0 = -1e30f, tm1 = -1e30f;
#pragma unroll
        for (int nt = 0; nt < 4; nt++) {
            tm0 = fmaxf(tm0, fmaxf(s[nt][0], s[nt][1]));
            tm1 = fmaxf(tm1, fmaxf(s[nt][2], s[nt][3]));
        }
        tm0 = fmaxf(tm0, __shfl_xor_sync(0xffffffffu, tm0, 1));
        tm0 = fmaxf(tm0, __shfl_xor_sync(0xffffffffu, tm0, 2));
        tm1 = fmaxf(tm1, __shfl_xor_sync(0xffffffffu, tm1, 1));
        tm1 = fmaxf(tm1, __shfl_xor_sync(0xffffffffu, tm1, 2));
        float nm0 = fmaxf(m0, tm0);
        float nm1 = fmaxf(m1, tm1);
        float corr0 = __expf(m0 - nm0);
        float corr1 = __expf(m1 - nm1);
        m0 = nm0; m1 = nm1;

        float rs0 = 0.f, rs1 = 0.f;
#pragma unroll
        for (int nt = 0; nt < 4; nt++) {
            float p0 = __expf(s[nt][0] - nm0);
            float p1 = __expf(s[nt][1] - nm0);
            float p2 = __expf(s[nt][2] - nm1);
            float p3 = __expf(s[nt][3] - nm1);
            rs0 += p0 + p1;
            rs1 += p2 + p3;
            // store P (tf32-rounded) to per-warp smem region
            float2 w0; w0.x = to_tf32(p0); w0.y = to_tf32(p1);
            float2 w1; w1.x = to_tf32(p2); w1.y = to_tf32(p3);
            *(float2*)&p_s[g * 36 + nt * 8 + 2 * tig]       = w0;
            *(float2*)&p_s[(g + 8) * 36 + nt * 8 + 2 * tig] = w1;
        }
        rs0 += __shfl_xor_sync(0xffffffffu, rs0, 1);
        rs0 += __shfl_xor_sync(0xffffffffu, rs0, 2);
        rs1 += __shfl_xor_sync(0xffffffffu, rs1, 1);
        rs1 += __shfl_xor_sync(0xffffffffu, rs1, 2);
        l0 = l0 * corr0 + rs0;
        l1 = l1 * corr1 + rs1;

#pragma unroll
        for (int nt = 0; nt < 8; nt++) {
            o[nt][0] *= corr0; o[nt][1] *= corr0;
            o[nt][2] *= corr1; o[nt][3] *= corr1;
        }
        __syncwarp();

        // ---- PV: o(16x64) += P(16x32) @ V(32x64), V-split (2 MMAs) ----
#pragma unroll
        for (int kk = 0; kk < 4; kk++) {
            uint32_t a0 = __float_as_uint(p_s[g * 36 + kk * 8 + tig]);
            uint32_t a1 = __float_as_uint(p_s[(g + 8) * 36 + kk * 8 + tig]);
            uint32_t a2 = __float_as_uint(p_s[g * 36 + kk * 8 + tig + 4]);
            uint32_t a3 = __float_as_uint(p_s[(g + 8) * 36 + kk * 8 + tig + 4]);
#pragma unroll
            for (int nt = 0; nt < 8; nt++) {
                uint32_t bh0 = __float_as_uint(vh_s[(kk * 8 + tig) * 72 + nt * 8 + g]);
                uint32_t bh1 = __float_as_uint(vh_s[(kk * 8 + tig + 4) * 72 + nt * 8 + g]);
                mma_tf32(o[nt][0], o[nt][1], o[nt][2], o[nt][3],
                         a0, a1, a2, a3, bh0, bh1);
                uint32_t bl0 = __float_as_uint(vl_s[(kk * 8 + tig) * 72 + nt * 8 + g]);
                uint32_t bl1 = __float_as_uint(vl_s[(kk * 8 + tig + 4) * 72 + nt * 8 + g]);
                mma_tf32(o[nt][0], o[nt][1], o[nt][2], o[nt][3],
                         a0, a1, a2, a3, bl0, bl1);
            }
        }
        __syncthreads();
    }

    // ---- finalize: out[b, s, h*64 + d] ----
    float inv0 = 1.f / l0;
    float inv1 = 1.f / l1;
    int s0 = qb + warp * 16 + g;
    int s1 = s0 + 8;
#pragma unroll
    for (int nt = 0; nt < 8; nt++) {
        int d = nt * 8 + 2 * tig;
        float2 w0; w0.x = o[nt][0] * inv0; w0.y = o[nt][1] * inv0;
        float2 w1; w1.x = o[nt][2] * inv1; w1.y = o[nt][3] * inv1;
        *(float2*)&out[((size_t)(b * S_ + s0) * H_ + h) * DV_ + d] = w0;
        *(float2*)&out[((size_t)(b * S_ + s1) * H_ + h) * DV_ + d] = w1;
    }
}

// ---------------------------------------------------------------------------
extern "C" void kernel_launch(void* const* d_in, const int* in_sizes, int n_in,
                              void* d_out, int out_size)
{
    const float* query = (const float*)d_in[0];
    const float* key   = (const float*)d_in[1];
    const float* value = (const float*)d_in[2];
    const int*   amask = (const int*)d_in[3];
    const float* wq = (const float*)d_in[4];
    const float* bq = (const float*)d_in[5];
    const float* wk = (const float*)d_in[6];
    const float* bk = (const float*)d_in[7];
    const float* wv = (const float*)d_in[8];
    const float* bv = (const float*)d_in[9];
    const float* wo = (const float*)d_in[10];
    const float* bo = (const float*)d_in[11];
    float* out = (float*)d_out;

    float *gq, *gk, *gv, *ga;
    cudaGetSymbolAddress((void**)&gq, g_q);
    cudaGetSymbolAddress((void**)&gk, g_k);
    cudaGetSymbolAddress((void**)&gv, g_v);
    cudaGetSymbolAddress((void**)&ga, g_a);

    const int M = B_ * S_;       // 8192
    const int N = H_ * DK_;      // 1024
    const int K = D_;            // 1024

    dim3 ggrid(N / 128, M / 128);

    gemm_tc<0><<<ggrid, 256>>>(query, wq, bq, gq, M, N, K);
    gemm_tc<0><<<ggrid, 256>>>(key,   wk, bk, gk, M, N, K);
    gemm_tc<0><<<ggrid, 256>>>(value, wv, bv, gv, M, N, K);

    dim3 agrid(S_ / 64, H_, B_);
    attn_tc<<<agrid, 128>>>(gq, gk, gv, amask, ga);

    gemm_tc<1><<<dim3(1024 / 128, M / 128), 256>>>(ga, wo, bo, out, M, 1024, H_ * DV_);
}

// round 4
// speedup vs baseline: 3.9137x; 1.4774x over previous
#include <cuda_runtime.h>
#include <math.h>
#include <stdint.h>

#define B_  4
#define S_  2048
#define D_  1024
#define H_  16
#define DK_ 64
#define DV_ 64

// Scratch (alloc-free rule: __device__ globals)
__device__ float g_q[B_*H_*S_*DK_];   // [B,H,S,DK]
__device__ float g_k[B_*H_*S_*DK_];   // [B,H,S,DK]
__device__ float g_v[B_*H_*S_*DV_];   // [B,H,S,DV]
__device__ float g_a[B_*S_*H_*DV_];   // [B,S,H*DV]
__device__ int   g_idx[B_*S_];        // compacted unmasked key indices
__device__ int   g_cnt[B_];           // count per batch

__device__ __forceinline__ float to_tf32(float x) {
    float r;
    asm("cvt.rna.tf32.f32 %0, %1;" : "=f"(r) : "f"(x));
    return r;
}

__device__ __forceinline__ void mma_tf32(float& d0, float& d1, float& d2, float& d3,
                                         uint32_t a0, uint32_t a1, uint32_t a2, uint32_t a3,
                                         uint32_t b0, uint32_t b1)
{
    asm volatile(
        "mma.sync.aligned.m16n8k8.row.col.f32.tf32.tf32.f32 "
        "{%0,%1,%2,%3}, {%4,%5,%6,%7}, {%8,%9}, {%0,%1,%2,%3};"
        : "+f"(d0), "+f"(d1), "+f"(d2), "+f"(d3)
        : "r"(a0), "r"(a1), "r"(a2), "r"(a3), "r"(b0), "r"(b1));
}

// ---------------------------------------------------------------------------
// Mask compaction: one warp per batch. Keys with mask==0 survive.
// ---------------------------------------------------------------------------
__global__ void compact_k(const int* __restrict__ mask)
{
    const int b = blockIdx.x;
    const int lane = threadIdx.x;
    int c = 0;
    for (int base = 0; base < S_; base += 32) {
        int mv = mask[b * S_ + base + lane];
        unsigned ball = __ballot_sync(0xffffffffu, mv == 0);
        int rank = __popc(ball & ((1u << lane) - 1));
        if (mv == 0) g_idx[b * S_ + c + rank] = base + lane;
        c += __popc(ball);
    }
    if (lane == 0) g_cnt[b] = c;
}

// ---------------------------------------------------------------------------
// tf32 tensor-core GEMM, double-buffered (reg-staged LDG -> STS).
// Block tile 128x128, k-step 16, 256 threads = 8 warps (2x4), warp tile 64x32.
// MODE 0: fused QKV (blockIdx.z selects input set), scatter-store [B,H,S,64]
// MODE 1: single GEMM, row-major store
// ---------------------------------------------------------------------------
#define PADG 136
template<int MODE>
__global__ __launch_bounds__(256)
void gemm_tc(const float* __restrict__ A0, const float* __restrict__ A1,
             const float* __restrict__ A2,
             const float* __restrict__ W0, const float* __restrict__ W1,
             const float* __restrict__ W2,
             const float* __restrict__ b0p, const float* __restrict__ b1p,
             const float* __restrict__ b2p,
             float* __restrict__ C0, float* __restrict__ C1, float* __restrict__ C2,
             int M, int N, int K)
{
    __shared__ float As[2][16 * PADG];
    __shared__ float Bs[2][16 * PADG];

    const int z = (MODE == 0) ? blockIdx.z : 0;
    const float* A    = (z == 0) ? A0 : (z == 1) ? A1 : A2;
    const float* W    = (z == 0) ? W0 : (z == 1) ? W1 : W2;
    const float* bias = (z == 0) ? b0p : (z == 1) ? b1p : b2p;
    float*       C    = (z == 0) ? C0 : (z == 1) ? C1 : C2;

    const int tid  = threadIdx.x;
    const int warp = tid >> 5;
    const int lane = tid & 31;
    const int g    = lane >> 2;
    const int tig  = lane & 3;
    const int wr   = warp >> 2;
    const int wc   = warp & 3;

    const int rBase = blockIdx.y * 128;
    const int cBase = blockIdx.x * 128;

    // per-thread staging indices
    const int ar0 = (tid * 2) >> 2,     aq0 = (tid * 2) & 3;       // A float4 #0
    const int ar1 = (tid * 2 + 1) >> 2, aq1 = (tid * 2 + 1) & 3;   // A float4 #1
    const int bk0 = tid >> 5,        bc0 = (tid & 31) * 4;          // B float4 #0
    const int bk1 = (tid + 256) >> 5, bc1 = bc0;                    // B float4 #1

    float4 ar[2], br[2];

    auto load_tile = [&](int k0) {
        ar[0] = *(const float4*)(A + (size_t)(rBase + ar0) * K + k0 + aq0 * 4);
        ar[1] = *(const float4*)(A + (size_t)(rBase + ar1) * K + k0 + aq1 * 4);
        br[0] = *(const float4*)(W + (size_t)(k0 + bk0) * N + cBase + bc0);
        br[1] = *(const float4*)(W + (size_t)(k0 + bk1) * N + cBase + bc1);
    };
    auto store_tile = [&](int buf) {
        float* as = As[buf];
        float* bs = Bs[buf];
        as[(aq0 * 4 + 0) * PADG + ar0] = to_tf32(ar[0].x);
        as[(aq0 * 4 + 1) * PADG + ar0] = to_tf32(ar[0].y);
        as[(aq0 * 4 + 2) * PADG + ar0] = to_tf32(ar[0].z);
        as[(aq0 * 4 + 3) * PADG + ar0] = to_tf32(ar[0].w);
        as[(aq1 * 4 + 0) * PADG + ar1] = to_tf32(ar[1].x);
        as[(aq1 * 4 + 1) * PADG + ar1] = to_tf32(ar[1].y);
        as[(aq1 * 4 + 2) * PADG + ar1] = to_tf32(ar[1].z);
        as[(aq1 * 4 + 3) * PADG + ar1] = to_tf32(ar[1].w);
        float4 cv;
        cv.x = to_tf32(br[0].x); cv.y = to_tf32(br[0].y);
        cv.z = to_tf32(br[0].z); cv.w = to_tf32(br[0].w);
        *(float4*)&bs[bk0 * PADG + bc0] = cv;
        cv.x = to_tf32(br[1].x); cv.y = to_tf32(br[1].y);
        cv.z = to_tf32(br[1].z); cv.w = to_tf32(br[1].w);
        *(float4*)&bs[bk1 * PADG + bc1] = cv;
    };

    float acc[4][4][4];
#pragma unroll
    for (int mt = 0; mt < 4; mt++)
#pragma unroll
        for (int nt = 0; nt < 4; nt++)
#pragma unroll
            for (int r = 0; r < 4; r++) acc[mt][nt][r] = 0.f;

    auto compute = [&](int buf) {
        const float* as = As[buf];
        const float* bs = Bs[buf];
#pragma unroll
        for (int ks = 0; ks < 2; ks++) {
            const int kb = ks * 8;
            uint32_t a[4][4];
#pragma unroll
            for (int mt = 0; mt < 4; mt++) {
                int row0 = wr * 64 + mt * 16;
                a[mt][0] = __float_as_uint(as[(kb + tig)     * PADG + row0 + g]);
                a[mt][1] = __float_as_uint(as[(kb + tig)     * PADG + row0 + g + 8]);
                a[mt][2] = __float_as_uint(as[(kb + tig + 4) * PADG + row0 + g]);
                a[mt][3] = __float_as_uint(as[(kb + tig + 4) * PADG + row0 + g + 8]);
            }
            uint32_t b[4][2];
#pragma unroll
            for (int nt = 0; nt < 4; nt++) {
                int col0 = wc * 32 + nt * 8;
                b[nt][0] = __float_as_uint(bs[(kb + tig)     * PADG + col0 + g]);
                b[nt][1] = __float_as_uint(bs[(kb + tig + 4) * PADG + col0 + g]);
            }
#pragma unroll
            for (int mt = 0; mt < 4; mt++)
#pragma unroll
                for (int nt = 0; nt < 4; nt++)
                    mma_tf32(acc[mt][nt][0], acc[mt][nt][1], acc[mt][nt][2], acc[mt][nt][3],
                             a[mt][0], a[mt][1], a[mt][2], a[mt][3],
                             b[nt][0], b[nt][1]);
        }
    };

    // pipeline: prologue
    load_tile(0);
    store_tile(0);
    __syncthreads();

    int buf = 0;
    for (int k0 = 16; k0 < K; k0 += 16) {
        load_tile(k0);
        compute(buf);
        store_tile(buf ^ 1);
        __syncthreads();
        buf ^= 1;
    }
    compute(buf);

    // epilogue
#pragma unroll
    for (int mt = 0; mt < 4; mt++) {
#pragma unroll
        for (int nt = 0; nt < 4; nt++) {
#pragma unroll
            for (int half = 0; half < 2; half++) {
                int r = rBase + wr * 64 + mt * 16 + g + half * 8;
                int c = cBase + wc * 32 + nt * 8 + tig * 2;
                float v0 = acc[mt][nt][half * 2 + 0] + bias[c];
                float v1 = acc[mt][nt][half * 2 + 1] + bias[c + 1];
                if (MODE == 0) {
                    int bb = r >> 11;
                    int s  = r & 2047;
                    int h  = c >> 6;
                    int dk = c & 63;
                    size_t base = (((size_t)(bb * H_ + h) * S_) + s) * DK_ + dk;
                    C[base]     = v0;
                    C[base + 1] = v1;
                } else {
                    C[(size_t)r * N + c]     = v0;
                    C[(size_t)r * N + c + 1] = v1;
                }
            }
        }
    }
}

// ---------------------------------------------------------------------------
// Tensor-core flash attention over COMPACTED keys (tf32 MMA, error-compensated).
// Block: 128 threads / 4 warps, 64 q-rows. Keys gathered via g_idx; tail padded
// with -1e9 bias (exp underflows to exactly 0, matching the fp32 reference).
// ---------------------------------------------------------------------------
#define KT 32

__global__ __launch_bounds__(128)
void attn_tc(const float* __restrict__ q, const float* __restrict__ k,
             const float* __restrict__ v, float* __restrict__ out)
{
    __shared__ float q_s[64 * 68];    // Q staging; later per-warp P (16x36 each)
    __shared__ float k_s[KT * 68];
    __shared__ float vh_s[KT * 72];
    __shared__ float vl_s[KT * 72];
    __shared__ float mn[KT];

    const int tid  = threadIdx.x;
    const int warp = tid >> 5;
    const int lane = tid & 31;
    const int g    = lane >> 2;
    const int tig  = lane & 3;

    const int qb = blockIdx.x * 64;
    const int h  = blockIdx.y;
    const int b  = blockIdx.z;

    const int  cnt  = g_cnt[b];
    const int* idxl = g_idx + b * S_;

    const float* qbh = q + ((size_t)(b * H_ + h) * S_) * DK_;
    const float* kbh = k + ((size_t)(b * H_ + h) * S_) * DK_;
    const float* vbh = v + ((size_t)(b * H_ + h) * S_) * DV_;

    // stage Q tile 64x64
#pragma unroll
    for (int t = 0; t < 8; t++) {
        int idx = tid + t * 128;
        int row = idx >> 4;
        int c4  = (idx & 15) * 4;
        float4 vv = *(const float4*)(qbh + (size_t)(qb + row) * DK_ + c4);
        *(float4*)&q_s[row * 68 + c4] = vv;
    }
    __syncthreads();

    // Q fragments, hi/lo split, register-resident
    uint32_t qhi[8][4], qlo[8][4];
    {
        const int r0 = warp * 16 + g;
        const int r1 = r0 + 8;
#pragma unroll
        for (int kt = 0; kt < 8; kt++) {
            float f0 = q_s[r0 * 68 + kt * 8 + tig];
            float f1 = q_s[r1 * 68 + kt * 8 + tig];
            float f2 = q_s[r0 * 68 + kt * 8 + tig + 4];
            float f3 = q_s[r1 * 68 + kt * 8 + tig + 4];
            float h0 = to_tf32(f0), h1 = to_tf32(f1), h2 = to_tf32(f2), h3 = to_tf32(f3);
            qhi[kt][0] = __float_as_uint(h0);
            qhi[kt][1] = __float_as_uint(h1);
            qhi[kt][2] = __float_as_uint(h2);
            qhi[kt][3] = __float_as_uint(h3);
            qlo[kt][0] = __float_as_uint(to_tf32(f0 - h0));
            qlo[kt][1] = __float_as_uint(to_tf32(f1 - h1));
            qlo[kt][2] = __float_as_uint(to_tf32(f2 - h2));
            qlo[kt][3] = __float_as_uint(to_tf32(f3 - h3));
        }
    }
    __syncthreads();
    float* p_s = q_s + warp * (16 * 36);

    float m0 = -1e30f, m1 = -1e30f, l0 = 0.f, l1 = 0.f;
    float o[8][4];
#pragma unroll
    for (int nt = 0; nt < 8; nt++)
#pragma unroll
        for (int r = 0; r < 4; r++) o[nt][r] = 0.f;

    const int nTiles = (cnt + KT - 1) / KT;
    for (int t = 0; t < nTiles; t++) {
        const int kt0 = t * KT;
        // gather K (tf32-rounded) and V (hi/lo) rows via compacted indices
#pragma unroll
        for (int tt = 0; tt < 4; tt++) {
            int idx = tid + tt * 128;
            int row = idx >> 4;
            int c4  = (idx & 15) * 4;
            int kp  = kt0 + row;
            int kidx = (kp < cnt) ? __ldg(idxl + kp) : 0;

            float4 kv = *(const float4*)(kbh + (size_t)kidx * DK_ + c4);
            float4 kh;
            kh.x = to_tf32(kv.x); kh.y = to_tf32(kv.y);
            kh.z = to_tf32(kv.z); kh.w = to_tf32(kv.w);
            *(float4*)&k_s[row * 68 + c4] = kh;

            float4 vv = *(const float4*)(vbh + (size_t)kidx * DV_ + c4);
            float4 vh, vl;
            vh.x = to_tf32(vv.x); vl.x = to_tf32(vv.x - vh.x);
            vh.y = to_tf32(vv.y); vl.y = to_tf32(vv.y - vh.y);
            vh.z = to_tf32(vv.z); vl.z = to_tf32(vv.z - vh.z);
            vh.w = to_tf32(vv.w); vl.w = to_tf32(vv.w - vh.w);
            *(float4*)&vh_s[row * 72 + c4] = vh;
            *(float4*)&vl_s[row * 72 + c4] = vl;
        }
        if (tid < KT)
            mn[tid] = (kt0 + tid < cnt) ? 0.f : -1.0e9f;
        __syncthreads();

        // ---- QK^T ----
        float s[4][4];
#pragma unroll
        for (int nt = 0; nt < 4; nt++)
#pragma unroll
            for (int r = 0; r < 4; r++) s[nt][r] = 0.f;

#pragma unroll
        for (int kt = 0; kt < 8; kt++) {
#pragma unroll
            for (int nt = 0; nt < 4; nt++) {
                uint32_t bb0 = __float_as_uint(k_s[(nt * 8 + g) * 68 + kt * 8 + tig]);
                uint32_t bb1 = __float_as_uint(k_s[(nt * 8 + g) * 68 + kt * 8 + tig + 4]);
                mma_tf32(s[nt][0], s[nt][1], s[nt][2], s[nt][3],
                         qhi[kt][0], qhi[kt][1], qhi[kt][2], qhi[kt][3], bb0, bb1);
                mma_tf32(s[nt][0], s[nt][1], s[nt][2], s[nt][3],
                         qlo[kt][0], qlo[kt][1], qlo[kt][2], qlo[kt][3], bb0, bb1);
            }
        }

#pragma unroll
        for (int nt = 0; nt < 4; nt++) {
            float ma = mn[nt * 8 + 2 * tig];
            float mb = mn[nt * 8 + 2 * tig + 1];
            s[nt][0] = s[nt][0] * 0.125f + ma;
            s[nt][1] = s[nt][1] * 0.125f + mb;
            s[nt][2] = s[nt][2] * 0.125f + ma;
            s[nt][3] = s[nt][3] * 0.125f + mb;
        }

        // ---- online softmax ----
        float tm0 = -1e30f, tm1 = -1e30f;
#pragma unroll
        for (int nt = 0; nt < 4; nt++) {
            tm0 = fmaxf(tm0, fmaxf(s[nt][0], s[nt][1]));
            tm1 = fmaxf(tm1, fmaxf(s[nt][2], s[nt][3]));
        }
        tm0 = fmaxf(tm0, __shfl_xor_sync(0xffffffffu, tm0, 1));
        tm0 = fmaxf(tm0, __shfl_xor_sync(0xffffffffu, tm0, 2));
        tm1 = fmaxf(tm1, __shfl_xor_sync(0xffffffffu, tm1, 1));
        tm1 = fmaxf(tm1, __shfl_xor_sync(0xffffffffu, tm1, 2));
        float nm0 = fmaxf(m0, tm0);
        float nm1 = fmaxf(m1, tm1);
        float corr0 = __expf(m0 - nm0);
        float corr1 = __expf(m1 - nm1);
        m0 = nm0; m1 = nm1;

        float rs0 = 0.f, rs1 = 0.f;
#pragma unroll
        for (int nt = 0; nt < 4; nt++) {
            float p0 = __expf(s[nt][0] - nm0);
            float p1 = __expf(s[nt][1] - nm0);
            float p2 = __expf(s[nt][2] - nm1);
            float p3 = __expf(s[nt][3] - nm1);
            rs0 += p0 + p1;
            rs1 += p2 + p3;
            float2 w0; w0.x = to_tf32(p0); w0.y = to_tf32(p1);
            float2 w1; w1.x = to_tf32(p2); w1.y = to_tf32(p3);
            *(float2*)&p_s[g * 36 + nt * 8 + 2 * tig]       = w0;
            *(float2*)&p_s[(g + 8) * 36 + nt * 8 + 2 * tig] = w1;
        }
        rs0 += __shfl_xor_sync(0xffffffffu, rs0, 1);
        rs0 += __shfl_xor_sync(0xffffffffu, rs0, 2);
        rs1 += __shfl_xor_sync(0xffffffffu, rs1, 1);
        rs1 += __shfl_xor_sync(0xffffffffu, rs1, 2);
        l0 = l0 * corr0 + rs0;
        l1 = l1 * corr1 + rs1;

#pragma unroll
        for (int nt = 0; nt < 8; nt++) {
            o[nt][0] *= corr0; o[nt][1] *= corr0;
            o[nt][2] *= corr1; o[nt][3] *= corr1;
        }
        __syncwarp();

        // ---- PV ----
#pragma unroll
        for (int kk = 0; kk < 4; kk++) {
            uint32_t a0 = __float_as_uint(p_s[g * 36 + kk * 8 + tig]);
            uint32_t a1 = __float_as_uint(p_s[(g + 8) * 36 + kk * 8 + tig]);
            uint32_t a2 = __float_as_uint(p_s[g * 36 + kk * 8 + tig + 4]);
            uint32_t a3 = __float_as_uint(p_s[(g + 8) * 36 + kk * 8 + tig + 4]);
#pragma unroll
            for (int nt = 0; nt < 8; nt++) {
                uint32_t bh0 = __float_as_uint(vh_s[(kk * 8 + tig) * 72 + nt * 8 + g]);
                uint32_t bh1 = __float_as_uint(vh_s[(kk * 8 + tig + 4) * 72 + nt * 8 + g]);
                mma_tf32(o[nt][0], o[nt][1], o[nt][2], o[nt][3],
                         a0, a1, a2, a3, bh0, bh1);
                uint32_t bl0 = __float_as_uint(vl_s[(kk * 8 + tig) * 72 + nt * 8 + g]);
                uint32_t bl1 = __float_as_uint(vl_s[(kk * 8 + tig + 4) * 72 + nt * 8 + g]);
                mma_tf32(o[nt][0], o[nt][1], o[nt][2], o[nt][3],
                         a0, a1, a2, a3, bl0, bl1);
            }
        }
        __syncthreads();
    }

    // ---- finalize ----
    float inv0 = 1.f / l0;
    float inv1 = 1.f / l1;
    int s0 = qb + warp * 16 + g;
    int s1 = s0 + 8;
#pragma unroll
    for (int nt = 0; nt < 8; nt++) {
        int d = nt * 8 + 2 * tig;
        float2 w0; w0.x = o[nt][0] * inv0; w0.y = o[nt][1] * inv0;
        float2 w1; w1.x = o[nt][2] * inv1; w1.y = o[nt][3] * inv1;
        *(float2*)&out[((size_t)(b * S_ + s0) * H_ + h) * DV_ + d] = w0;
        *(float2*)&out[((size_t)(b * S_ + s1) * H_ + h) * DV_ + d] = w1;
    }
}

// ---------------------------------------------------------------------------
extern "C" void kernel_launch(void* const* d_in, const int* in_sizes, int n_in,
                              void* d_out, int out_size)
{
    const float* query = (const float*)d_in[0];
    const float* key   = (const float*)d_in[1];
    const float* value = (const float*)d_in[2];
    const int*   amask = (const int*)d_in[3];
    const float* wq = (const float*)d_in[4];
    const float* bq = (const float*)d_in[5];
    const float* wk = (const float*)d_in[6];
    const float* bk = (const float*)d_in[7];
    const float* wv = (const float*)d_in[8];
    const float* bv = (const float*)d_in[9];
    const float* wo = (const float*)d_in[10];
    const float* bo = (const float*)d_in[11];
    float* out = (float*)d_out;

    float *gq, *gk, *gv, *ga;
    cudaGetSymbolAddress((void**)&gq, g_q);
    cudaGetSymbolAddress((void**)&gk, g_k);
    cudaGetSymbolAddress((void**)&gv, g_v);
    cudaGetSymbolAddress((void**)&ga, g_a);

    const int M = B_ * S_;       // 8192
    const int N = H_ * DK_;      // 1024
    const int K = D_;            // 1024

    compact_k<<<B_, 32>>>(amask);

    dim3 ggrid(N / 128, M / 128, 3);
    gemm_tc<0><<<ggrid, 256>>>(query, key, value,
                               wq, wk, wv,
                               bq, bk, bv,
                               gq, gk, gv, M, N, K);

    dim3 agrid(S_ / 64, H_, B_);
    attn_tc<<<agrid, 128>>>(gq, gk, gv, ga);

    gemm_tc<1><<<dim3(1024 / 128, M / 128, 1), 256>>>(ga, ga, ga,
                                                      wo, wo, wo,
                                                      bo, bo, bo,
                                                      out, out, out, M, 1024, H_ * DV_);
}

// round 9
// speedup vs baseline: 4.4893x; 1.1471x over previous
#include <cuda_runtime.h>
#include <math.h>
#include <stdint.h>

#define B_  4
#define S_  2048
#define D_  1024
#define H_  16
#define DK_ 64
#define DV_ 64

// Scratch (alloc-free rule: __device__ globals)
__device__ float g_q[B_*H_*S_*DK_];   // [B,H,S,DK]
__device__ float g_k[B_*H_*S_*DK_];   // [B,H,S,DK]
__device__ float g_v[B_*H_*S_*DV_];   // [B,H,S,DV]
__device__ float g_a[B_*S_*H_*DV_];   // [B,S,H*DV]
__device__ int   g_idx[B_*S_];        // compacted unmasked key indices
__device__ int   g_cnt[B_];           // count per batch

__device__ __forceinline__ float to_tf32(float x) {
    float r;
    asm("cvt.rna.tf32.f32 %0, %1;" : "=f"(r) : "f"(x));
    return r;
}
__device__ __forceinline__ uint32_t tf32_bits(float x) {
    return __float_as_uint(to_tf32(x));
}

__device__ __forceinline__ void mma_tf32(float& d0, float& d1, float& d2, float& d3,
                                         uint32_t a0, uint32_t a1, uint32_t a2, uint32_t a3,
                                         uint32_t b0, uint32_t b1)
{
    asm volatile(
        "mma.sync.aligned.m16n8k8.row.col.f32.tf32.tf32.f32 "
        "{%0,%1,%2,%3}, {%4,%5,%6,%7}, {%8,%9}, {%0,%1,%2,%3};"
        : "+f"(d0), "+f"(d1), "+f"(d2), "+f"(d3)
        : "r"(a0), "r"(a1), "r"(a2), "r"(a3), "r"(b0), "r"(b1));
}

__device__ __forceinline__ void cp16(uint32_t dst_smem, const void* src) {
    asm volatile("cp.async.cg.shared.global [%0], [%1], 16;" :: "r"(dst_smem), "l"(src));
}
__device__ __forceinline__ void cp_commit() {
    asm volatile("cp.async.commit_group;");
}
template<int N>
__device__ __forceinline__ void cp_wait() {
    asm volatile("cp.async.wait_group %0;" :: "n"(N));
}

// ---------------------------------------------------------------------------
// Mask compaction: one warp per batch. Keys with mask==0 survive.
// ---------------------------------------------------------------------------
__global__ void compact_k(const int* __restrict__ mask)
{
    const int b = blockIdx.x;
    const int lane = threadIdx.x;
    int c = 0;
    for (int base = 0; base < S_; base += 32) {
        int mv = mask[b * S_ + base + lane];
        unsigned ball = __ballot_sync(0xffffffffu, mv == 0);
        int rank = __popc(ball & ((1u << lane) - 1));
        if (mv == 0) g_idx[b * S_ + c + rank] = base + lane;
        c += __popc(ball);
    }
    if (lane == 0) g_cnt[b] = c;
}

// ---------------------------------------------------------------------------
// tf32 tensor-core GEMM, cp.async double-buffered, raw fp32 smem,
// cvt.rna.tf32 at fragment read.
// Block tile 128x128, k-step 16, 256 threads = 8 warps (2x4), warp tile 64x32.
// As: [row][k] stride 20 ; Bs: [k][col] stride 132 (both conflict-free).
// MODE 0: fused QKV (blockIdx.z selects set), scatter-store [B,H,S,64]
// MODE 1: single GEMM, row-major store
// ---------------------------------------------------------------------------
#define ASTRIDE 20
#define BSTRIDE 132
template<int MODE>
__global__ __launch_bounds__(256)
void gemm_tc(const float* __restrict__ A0, const float* __restrict__ A1,
             const float* __restrict__ A2,
             const float* __restrict__ W0, const float* __restrict__ W1,
             const float* __restrict__ W2,
             const float* __restrict__ b0p, const float* __restrict__ b1p,
             const float* __restrict__ b2p,
             float* __restrict__ C0, float* __restrict__ C1, float* __restrict__ C2,
             int M, int N, int K)
{
    __shared__ __align__(16) float As[2][128 * ASTRIDE];
    __shared__ __align__(16) float Bs[2][16 * BSTRIDE];

    const int z = (MODE == 0) ? blockIdx.z : 0;
    const float* A    = (z == 0) ? A0 : (z == 1) ? A1 : A2;
    const float* W    = (z == 0) ? W0 : (z == 1) ? W1 : W2;
    const float* bias = (z == 0) ? b0p : (z == 1) ? b1p : b2p;
    float*       C    = (z == 0) ? C0 : (z == 1) ? C1 : C2;

    const int tid  = threadIdx.x;
    const int warp = tid >> 5;
    const int lane = tid & 31;
    const int g    = lane >> 2;
    const int tig  = lane & 3;
    const int wr   = warp >> 2;
    const int wc   = warp & 3;

    const int rBase = blockIdx.y * 128;
    const int cBase = blockIdx.x * 128;

    const uint32_t asb[2] = { (uint32_t)__cvta_generic_to_shared(As[0]),
                              (uint32_t)__cvta_generic_to_shared(As[1]) };
    const uint32_t bsb[2] = { (uint32_t)__cvta_generic_to_shared(Bs[0]),
                              (uint32_t)__cvta_generic_to_shared(Bs[1]) };

    auto issue = [&](int k0, int buf) {
#pragma unroll
        for (int j = 0; j < 2; j++) {
            int idx = tid + j * 256;          // A: 512 chunks of 16B
            int r   = idx >> 2;
            int qq  = idx & 3;
            cp16(asb[buf] + (r * ASTRIDE + qq * 4) * 4,
                 A + (size_t)(rBase + r) * K + k0 + qq * 4);
        }
#pragma unroll
        for (int j = 0; j < 2; j++) {
            int idx = tid + j * 256;          // B: 512 chunks
            int kr  = idx >> 5;
            int c4  = (idx & 31) * 4;
            cp16(bsb[buf] + (kr * BSTRIDE + c4) * 4,
                 W + (size_t)(k0 + kr) * N + cBase + c4);
        }
        cp_commit();
    };

    float acc[4][4][4];
#pragma unroll
    for (int mt = 0; mt < 4; mt++)
#pragma unroll
        for (int nt = 0; nt < 4; nt++)
#pragma unroll
            for (int r = 0; r < 4; r++) acc[mt][nt][r] = 0.f;

    auto compute = [&](int buf) {
        const float* as = As[buf];
        const float* bs = Bs[buf];
#pragma unroll
        for (int ks = 0; ks < 2; ks++) {
            const int kb = ks * 8;
            uint32_t a[4][4];
#pragma unroll
            for (int mt = 0; mt < 4; mt++) {
                int row0 = wr * 64 + mt * 16;
                a[mt][0] = tf32_bits(as[(row0 + g)     * ASTRIDE + kb + tig]);
                a[mt][1] = tf32_bits(as[(row0 + g + 8) * ASTRIDE + kb + tig]);
                a[mt][2] = tf32_bits(as[(row0 + g)     * ASTRIDE + kb + tig + 4]);
                a[mt][3] = tf32_bits(as[(row0 + g + 8) * ASTRIDE + kb + tig + 4]);
            }
            uint32_t b[4][2];
#pragma unroll
            for (int nt = 0; nt < 4; nt++) {
                int col0 = wc * 32 + nt * 8;
                b[nt][0] = tf32_bits(bs[(kb + tig)     * BSTRIDE + col0 + g]);
                b[nt][1] = tf32_bits(bs[(kb + tig + 4) * BSTRIDE + col0 + g]);
            }
#pragma unroll
            for (int mt = 0; mt < 4; mt++)
#pragma unroll
                for (int nt = 0; nt < 4; nt++)
                    mma_tf32(acc[mt][nt][0], acc[mt][nt][1], acc[mt][nt][2], acc[mt][nt][3],
                             a[mt][0], a[mt][1], a[mt][2], a[mt][3],
                             b[nt][0], b[nt][1]);
        }
    };

    issue(0, 0);
    int buf = 0;
    for (int k0 = 16; k0 < K; k0 += 16) {
        issue(k0, buf ^ 1);
        cp_wait<1>();
        __syncthreads();
        compute(buf);
        __syncthreads();
        buf ^= 1;
    }
    cp_wait<0>();
    __syncthreads();
    compute(buf);

    // epilogue
#pragma unroll
    for (int mt = 0; mt < 4; mt++) {
#pragma unroll
        for (int nt = 0; nt < 4; nt++) {
#pragma unroll
            for (int half = 0; half < 2; half++) {
                int r = rBase + wr * 64 + mt * 16 + g + half * 8;
                int c = cBase + wc * 32 + nt * 8 + tig * 2;
                float v0 = acc[mt][nt][half * 2 + 0] + bias[c];
                float v1 = acc[mt][nt][half * 2 + 1] + bias[c + 1];
                if (MODE == 0) {
                    int bb = r >> 11;
                    int s  = r & 2047;
                    int h  = c >> 6;
                    int dk = c & 63;
                    size_t base = (((size_t)(bb * H_ + h) * S_) + s) * DK_ + dk;
                    C[base]     = v0;
                    C[base + 1] = v1;
                } else {
                    C[(size_t)r * N + c]     = v0;
                    C[(size_t)r * N + c + 1] = v1;
                }
            }
        }
    }
}

// ---------------------------------------------------------------------------
// Tensor-core flash attention over COMPACTED keys.
// tf32 MMA; QK^T error-compensated (Q hi/lo), PV single-rounded.
// 128 threads / 4 warps, 64 q-rows per block. cp.async double-buffered K/V
// gather (raw fp32, cvt at fragment read). Q fragments direct from gmem,
// pre-scaled by 1/8. Tail keys masked by select (exp -> exact 0).
// ---------------------------------------------------------------------------
#define KT 32

__global__ __launch_bounds__(128)
void attn_tc(const float* __restrict__ q, const float* __restrict__ k,
             const float* __restrict__ v, float* __restrict__ out)
{
    __shared__ __align__(16) float k_s[2][KT * 68];
    __shared__ __align__(16) float v_s[2][KT * 72];
    __shared__ float p_sm[4][16 * 36];

    const int tid  = threadIdx.x;
    const int warp = tid >> 5;
    const int lane = tid & 31;
    const int g    = lane >> 2;
    const int tig  = lane & 3;

    const int qb = blockIdx.x * 64;
    const int h  = blockIdx.y;
    const int b  = blockIdx.z;

    const int  cnt  = g_cnt[b];
    const int* idxl = g_idx + b * S_;

    const float* qbh = q + ((size_t)(b * H_ + h) * S_) * DK_;
    const float* kbh = k + ((size_t)(b * H_ + h) * S_) * DK_;
    const float* vbh = v + ((size_t)(b * H_ + h) * S_) * DV_;

    const uint32_t ksb[2] = { (uint32_t)__cvta_generic_to_shared(k_s[0]),
                              (uint32_t)__cvta_generic_to_shared(k_s[1]) };
    const uint32_t vsb[2] = { (uint32_t)__cvta_generic_to_shared(v_s[0]),
                              (uint32_t)__cvta_generic_to_shared(v_s[1]) };

    const int nTiles = (cnt + KT - 1) / KT;

    auto issue_tile = [&](int t, int buf) {
#pragma unroll
        for (int tt = 0; tt < 4; tt++) {
            int idx = tid + tt * 128;         // 0..511 chunks (16 per row)
            int row = idx >> 4;
            int c4  = (idx & 15) * 4;
            int kp  = t * KT + row;
            int kidx = (kp < cnt) ? __ldg(idxl + kp) : 0;
            cp16(ksb[buf] + (row * 68 + c4) * 4, kbh + (size_t)kidx * DK_ + c4);
            cp16(vsb[buf] + (row * 72 + c4) * 4, vbh + (size_t)kidx * DV_ + c4);
        }
        cp_commit();
    };

    issue_tile(0, 0);

    // Q fragments direct from gmem, scaled by 1/8, hi/lo split
    uint32_t qhi[8][4], qlo[8][4];
    {
        const int r0 = qb + warp * 16 + g;
        const int r1 = r0 + 8;
#pragma unroll
        for (int kt = 0; kt < 8; kt++) {
            float f0 = qbh[(size_t)r0 * DK_ + kt * 8 + tig]     * 0.125f;
            float f1 = qbh[(size_t)r1 * DK_ + kt * 8 + tig]     * 0.125f;
            float f2 = qbh[(size_t)r0 * DK_ + kt * 8 + tig + 4] * 0.125f;
            float f3 = qbh[(size_t)r1 * DK_ + kt * 8 + tig + 4] * 0.125f;
            float h0 = to_tf32(f0), h1 = to_tf32(f1), h2 = to_tf32(f2), h3 = to_tf32(f3);
            qhi[kt][0] = __float_as_uint(h0);
            qhi[kt][1] = __float_as_uint(h1);
            qhi[kt][2] = __float_as_uint(h2);
            qhi[kt][3] = __float_as_uint(h3);
            qlo[kt][0] = tf32_bits(f0 - h0);
            qlo[kt][1] = tf32_bits(f1 - h1);
            qlo[kt][2] = tf32_bits(f2 - h2);
            qlo[kt][3] = tf32_bits(f3 - h3);
        }
    }
    float* p_s = p_sm[warp];

    float m0 = -1e30f, m1 = -1e30f, l0 = 0.f, l1 = 0.f;
    float o[8][4];
#pragma unroll
    for (int nt = 0; nt < 8; nt++)
#pragma unroll
        for (int r = 0; r < 4; r++) o[nt][r] = 0.f;

    for (int t = 0; t < nTiles; t++) {
        const int kt0 = t * KT;
        if (t + 1 < nTiles) issue_tile(t + 1, (t + 1) & 1);
        else cp_commit();
        cp_wait<1>();
        __syncthreads();

        const int buf = t & 1;
        const float* ks = k_s[buf];
        const float* vs = v_s[buf];

        // ---- QK^T : per-warp 16x32 scores (Q hi/lo compensated) ----
        float s[4][4];
#pragma unroll
        for (int nt = 0; nt < 4; nt++)
#pragma unroll
            for (int r = 0; r < 4; r++) s[nt][r] = 0.f;

#pragma unroll
        for (int kt = 0; kt < 8; kt++) {
#pragma unroll
            for (int nt = 0; nt < 4; nt++) {
                uint32_t bb0 = tf32_bits(ks[(nt * 8 + g) * 68 + kt * 8 + tig]);
                uint32_t bb1 = tf32_bits(ks[(nt * 8 + g) * 68 + kt * 8 + tig + 4]);
                mma_tf32(s[nt][0], s[nt][1], s[nt][2], s[nt][3],
                         qhi[kt][0], qhi[kt][1], qhi[kt][2], qhi[kt][3], bb0, bb1);
                mma_tf32(s[nt][0], s[nt][1], s[nt][2], s[nt][3],
                         qlo[kt][0], qlo[kt][1], qlo[kt][2], qlo[kt][3], bb0, bb1);
            }
        }

        // tail mask via select (padded rows must not win the max)
#pragma unroll
        for (int nt = 0; nt < 4; nt++) {
            int c0 = kt0 + nt * 8 + 2 * tig;
            int c1 = c0 + 1;
            if (c0 >= cnt) { s[nt][0] = -1e30f; s[nt][2] = -1e30f; }
            if (c1 >= cnt) { s[nt][1] = -1e30f; s[nt][3] = -1e30f; }
        }

        // ---- online softmax (rows g, g+8) ----
        float tm0 = -1e30f, tm1 = -1e30f;
#pragma unroll
        for (int nt = 0; nt < 4; nt++) {
            tm0 = fmaxf(tm0, fmaxf(s[nt][0], s[nt][1]));
            tm1 = fmaxf(tm1, fmaxf(s[nt][2], s[nt][3]));
        }
        tm0 = fmaxf(tm0, __shfl_xor_sync(0xffffffffu, tm0, 1));
        tm0 = fmaxf(tm0, __shfl_xor_sync(0xffffffffu, tm0, 2));
        tm1 = fmaxf(tm1, __shfl_xor_sync(0xffffffffu, tm1, 1));
        tm1 = fmaxf(tm1, __shfl_xor_sync(0xffffffffu, tm1, 2));
        float nm0 = fmaxf(m0, tm0);
        float nm1 = fmaxf(m1, tm1);
        float corr0 = __expf(m0 - nm0);
        float corr1 = __expf(m1 - nm1);
        m0 = nm0; m1 = nm1;

        float rs0 = 0.f, rs1 = 0.f;
#pragma unroll
        for (int nt = 0; nt < 4; nt++) {
            float p0 = __expf(s[nt][0] - nm0);
            float p1 = __expf(s[nt][1] - nm0);
            float p2 = __expf(s[nt][2] - nm1);
            float p3 = __expf(s[nt][3] - nm1);
            rs0 += p0 + p1;
            rs1 += p2 + p3;
            float2 w0; w0.x = to_tf32(p0); w0.y = to_tf32(p1);
            float2 w1; w1.x = to_tf32(p2); w1.y = to_tf32(p3);
            *(float2*)&p_s[g * 36 + nt * 8 + 2 * tig]       = w0;
            *(float2*)&p_s[(g + 8) * 36 + nt * 8 + 2 * tig] = w1;
        }
        rs0 += __shfl_xor_sync(0xffffffffu, rs0, 1);
        rs0 += __shfl_xor_sync(0xffffffffu, rs0, 2);
        rs1 += __shfl_xor_sync(0xffffffffu, rs1, 1);
        rs1 += __shfl_xor_sync(0xffffffffu, rs1, 2);
        l0 = l0 * corr0 + rs0;
        l1 = l1 * corr1 + rs1;

#pragma unroll
        for (int nt = 0; nt < 8; nt++) {
            o[nt][0] *= corr0; o[nt][1] *= corr0;
            o[nt][2] *= corr1; o[nt][3] *= corr1;
        }
        __syncwarp();

        // ---- PV : o(16x64) += P(16x32) @ V(32x64), single MMA ----
#pragma unroll
        for (int kk = 0; kk < 4; kk++) {
            uint32_t a0 = __float_as_uint(p_s[g * 36 + kk * 8 + tig]);
            uint32_t a1 = __float_as_uint(p_s[(g + 8) * 36 + kk * 8 + tig]);
            uint32_t a2 = __float_as_uint(p_s[g * 36 + kk * 8 + tig + 4]);
            uint32_t a3 = __float_as_uint(p_s[(g + 8) * 36 + kk * 8 + tig + 4]);
#pragma unroll
            for (int nt = 0; nt < 8; nt++) {
                uint32_t bv0 = tf32_bits(vs[(kk * 8 + tig) * 72 + nt * 8 + g]);
                uint32_t bv1 = tf32_bits(vs[(kk * 8 + tig + 4) * 72 + nt * 8 + g]);
                mma_tf32(o[nt][0], o[nt][1], o[nt][2], o[nt][3],
                         a0, a1, a2, a3, bv0, bv1);
            }
        }
        __syncthreads();
    }

    // ---- finalize: out[b, s, h*64 + d] ----
    float inv0 = 1.f / l0;
    float inv1 = 1.f / l1;
    int s0 = qb + warp * 16 + g;
    int s1 = s0 + 8;
#pragma unroll
    for (int nt = 0; nt < 8; nt++) {
        int d = nt * 8 + 2 * tig;
        float2 w0; w0.x = o[nt][0] * inv0; w0.y = o[nt][1] * inv0;
        float2 w1; w1.x = o[nt][2] * inv1; w1.y = o[nt][3] * inv1;
        *(float2*)&out[((size_t)(b * S_ + s0) * H_ + h) * DV_ + d] = w0;
        *(float2*)&out[((size_t)(b * S_ + s1) * H_ + h) * DV_ + d] = w1;
    }
}

// ---------------------------------------------------------------------------
extern "C" void kernel_launch(void* const* d_in, const int* in_sizes, int n_in,
                              void* d_out, int out_size)
{
    const float* query = (const float*)d_in[0];
    const float* key   = (const float*)d_in[1];
    const float* value = (const float*)d_in[2];
    const int*   amask = (const int*)d_in[3];
    const float* wq = (const float*)d_in[4];
    const float* bq = (const float*)d_in[5];
    const float* wk = (const float*)d_in[6];
    const float* bk = (const float*)d_in[7];
    const float* wv = (const float*)d_in[8];
    const float* bv = (const float*)d_in[9];
    const float* wo = (const float*)d_in[10];
    const float* bo = (const float*)d_in[11];
    float* out = (float*)d_out;

    float *gq, *gk, *gv, *ga;
    cudaGetSymbolAddress((void**)&gq, g_q);
    cudaGetSymbolAddress((void**)&gk, g_k);
    cudaGetSymbolAddress((void**)&gv, g_v);
    cudaGetSymbolAddress((void**)&ga, g_a);

    const int M = B_ * S_;       // 8192
    const int N = H_ * DK_;      // 1024
    const int K = D_;            // 1024

    compact_k<<<B_, 32>>>(amask);

    dim3 ggrid(N / 128, M / 128, 3);
    gemm_tc<0><<<ggrid, 256>>>(query, key, value,
                               wq, wk, wv,
                               bq, bk, bv,
                               gq, gk, gv, M, N, K);

    dim3 agrid(S_ / 64, H_, B_);
    attn_tc<<<agrid, 128>>>(gq, gk, gv, ga);

    gemm_tc<1><<<dim3(1024 / 128, M / 128, 1), 256>>>(ga, ga, ga,
                                                      wo, wo, wo,
                                                      bo, bo, bo,
                                                      out, out, out, M, 1024, H_ * DV_);
}

// round 10
// speedup vs baseline: 4.4993x; 1.0022x over previous
#include <cuda_runtime.h>
#include <math.h>
#include <stdint.h>

#define B_  4
#define S_  2048
#define D_  1024
#define H_  16
#define DK_ 64
#define DV_ 64

// Scratch (alloc-free rule: __device__ globals)
__device__ float g_q[B_*H_*S_*DK_];   // [B,H,S,DK] fp32 (raw)
__device__ float g_k[B_*H_*S_*DK_];   // [B,H,S,DK] tf32-rounded
__device__ float g_v[B_*H_*S_*DV_];   // [B,H,S,DV] tf32-rounded
__device__ float g_a[B_*S_*H_*DV_];   // [B,S,H*DV] tf32-rounded
__device__ float g_qc[B_*S_*D_];      // rounded copy of query
__device__ float g_kc[B_*S_*D_];      // rounded copy of key
__device__ float g_vc[B_*S_*D_];      // rounded copy of value
__device__ float g_wqr[D_*H_*DK_];
__device__ float g_wkr[D_*H_*DK_];
__device__ float g_wvr[D_*H_*DV_];
__device__ float g_wor[H_*DV_*D_];
__device__ int   g_idx[B_*S_];        // compacted unmasked key indices
__device__ int   g_cnt[B_];           // count per batch

__device__ __forceinline__ float to_tf32(float x) {
    float r;
    asm("cvt.rna.tf32.f32 %0, %1;" : "=f"(r) : "f"(x));
    return r;
}

__device__ __forceinline__ void mma_tf32(float& d0, float& d1, float& d2, float& d3,
                                         uint32_t a0, uint32_t a1, uint32_t a2, uint32_t a3,
                                         uint32_t b0, uint32_t b1)
{
    asm volatile(
        "mma.sync.aligned.m16n8k8.row.col.f32.tf32.tf32.f32 "
        "{%0,%1,%2,%3}, {%4,%5,%6,%7}, {%8,%9}, {%0,%1,%2,%3};"
        : "+f"(d0), "+f"(d1), "+f"(d2), "+f"(d3)
        : "r"(a0), "r"(a1), "r"(a2), "r"(a3), "r"(b0), "r"(b1));
}

__device__ __forceinline__ void ldsm_x4(uint32_t& r0, uint32_t& r1, uint32_t& r2, uint32_t& r3,
                                        uint32_t addr)
{
    asm volatile("ldmatrix.sync.aligned.m8n8.x4.shared.b16 {%0,%1,%2,%3}, [%4];"
                 : "=r"(r0), "=r"(r1), "=r"(r2), "=r"(r3) : "r"(addr));
}

__device__ __forceinline__ void cp16(uint32_t dst_smem, const void* src) {
    asm volatile("cp.async.cg.shared.global [%0], [%1], 16;" :: "r"(dst_smem), "l"(src));
}
__device__ __forceinline__ void cp_commit() {
    asm volatile("cp.async.commit_group;");
}
template<int N>
__device__ __forceinline__ void cp_wait() {
    asm volatile("cp.async.wait_group %0;" :: "n"(N));
}

// ---------------------------------------------------------------------------
// Mask compaction: one warp per batch. Keys with mask==0 survive.
// ---------------------------------------------------------------------------
__global__ void compact_k(const int* __restrict__ mask)
{
    const int b = blockIdx.x;
    const int lane = threadIdx.x;
    int c = 0;
    for (int base = 0; base < S_; base += 32) {
        int mv = mask[b * S_ + base + lane];
        unsigned ball = __ballot_sync(0xffffffffu, mv == 0);
        int rank = __popc(ball & ((1u << lane) - 1));
        if (mv == 0) g_idx[b * S_ + c + rank] = base + lane;
        c += __popc(ball);
    }
    if (lane == 0) g_cnt[b] = c;
}

// ---------------------------------------------------------------------------
// Pre-round to tf32 (rna), vectorized. blockIdx.y selects the tensor.
// ---------------------------------------------------------------------------
__global__ void round_k(const float* __restrict__ s0, const float* __restrict__ s1,
                        const float* __restrict__ s2, const float* __restrict__ s3,
                        float* __restrict__ d0, float* __restrict__ d1,
                        float* __restrict__ d2, float* __restrict__ d3, int n4)
{
    const int z = blockIdx.y;
    const float* s = (z == 0) ? s0 : (z == 1) ? s1 : (z == 2) ? s2 : s3;
    float*       d = (z == 0) ? d0 : (z == 1) ? d1 : (z == 2) ? d2 : d3;
    const int stride = gridDim.x * blockDim.x;
    for (int i = blockIdx.x * blockDim.x + threadIdx.x; i < n4; i += stride) {
        float4 v = ((const float4*)s)[i];
        v.x = to_tf32(v.x); v.y = to_tf32(v.y);
        v.z = to_tf32(v.z); v.w = to_tf32(v.w);
        ((float4*)d)[i] = v;
    }
}

// ---------------------------------------------------------------------------
// tf32 tensor-core GEMM. Inputs PRE-ROUNDED to tf32 -> no cvt anywhere.
// cp.async double-buffered. A fragments via ldmatrix.x4, B via scalar LDS.
// Block tile 128x128, k-step 16, 256 threads = 8 warps (2x4), warp tile 64x32.
// As: [row][k] stride 20 ; Bs: [k][col] stride 132 (both conflict-free).
// MODE 0: fused QKV (z selects set), scatter-store [B,H,S,64];
//         z=1,2 (K,V) stored tf32-rounded, z=0 (Q) raw fp32.
// MODE 1: single GEMM, row-major store.
// ---------------------------------------------------------------------------
#define ASTRIDE 20
#define BSTRIDE 132
template<int MODE>
__global__ __launch_bounds__(256)
void gemm_tc(const float* __restrict__ A0, const float* __restrict__ A1,
             const float* __restrict__ A2,
             const float* __restrict__ W0, const float* __restrict__ W1,
             const float* __restrict__ W2,
             const float* __restrict__ b0p, const float* __restrict__ b1p,
             const float* __restrict__ b2p,
             float* __restrict__ C0, float* __restrict__ C1, float* __restrict__ C2,
             int M, int N, int K)
{
    __shared__ __align__(16) float As[2][128 * ASTRIDE];
    __shared__ __align__(16) float Bs[2][16 * BSTRIDE];

    const int z = (MODE == 0) ? blockIdx.z : 0;
    const float* A    = (z == 0) ? A0 : (z == 1) ? A1 : A2;
    const float* W    = (z == 0) ? W0 : (z == 1) ? W1 : W2;
    const float* bias = (z == 0) ? b0p : (z == 1) ? b1p : b2p;
    float*       C    = (z == 0) ? C0 : (z == 1) ? C1 : C2;

    const int tid  = threadIdx.x;
    const int warp = tid >> 5;
    const int lane = tid & 31;
    const int g    = lane >> 2;
    const int tig  = lane & 3;
    const int wr   = warp >> 2;
    const int wc   = warp & 3;

    const int rBase = blockIdx.y * 128;
    const int cBase = blockIdx.x * 128;

    const uint32_t asb[2] = { (uint32_t)__cvta_generic_to_shared(As[0]),
                              (uint32_t)__cvta_generic_to_shared(As[1]) };
    const uint32_t bsb[2] = { (uint32_t)__cvta_generic_to_shared(Bs[0]),
                              (uint32_t)__cvta_generic_to_shared(Bs[1]) };

    // per-lane ldmatrix offset: m = lane&15 (within 16-row tile), k = (lane>>4)*4
    const uint32_t aoff = (((lane & 15) * ASTRIDE) + ((lane >> 4) << 2)) * 4;

    auto issue = [&](int k0, int buf) {
#pragma unroll
        for (int j = 0; j < 2; j++) {
            int idx = tid + j * 256;          // A: 512 chunks of 16B
            int r   = idx >> 2;
            int qq  = idx & 3;
            cp16(asb[buf] + (r * ASTRIDE + qq * 4) * 4,
                 A + (size_t)(rBase + r) * K + k0 + qq * 4);
        }
#pragma unroll
        for (int j = 0; j < 2; j++) {
            int idx = tid + j * 256;          // B: 512 chunks
            int kr  = idx >> 5;
            int c4  = (idx & 31) * 4;
            cp16(bsb[buf] + (kr * BSTRIDE + c4) * 4,
                 W + (size_t)(k0 + kr) * N + cBase + c4);
        }
        cp_commit();
    };

    float acc[4][4][4];
#pragma unroll
    for (int mt = 0; mt < 4; mt++)
#pragma unroll
        for (int nt = 0; nt < 4; nt++)
#pragma unroll
            for (int r = 0; r < 4; r++) acc[mt][nt][r] = 0.f;

    auto compute = [&](int buf) {
        const uint32_t as = asb[buf];
        const float* bs = Bs[buf];
#pragma unroll
        for (int ks = 0; ks < 2; ks++) {
            const int kb = ks * 8;
            uint32_t a[4][4];
#pragma unroll
            for (int mt = 0; mt < 4; mt++) {
                int row0 = wr * 64 + mt * 16;
                ldsm_x4(a[mt][0], a[mt][1], a[mt][2], a[mt][3],
                        as + (uint32_t)(row0 * ASTRIDE + kb) * 4 + aoff);
            }
            uint32_t b[4][2];
#pragma unroll
            for (int nt = 0; nt < 4; nt++) {
                int col0 = wc * 32 + nt * 8;
                b[nt][0] = __float_as_uint(bs[(kb + tig)     * BSTRIDE + col0 + g]);
                b[nt][1] = __float_as_uint(bs[(kb + tig + 4) * BSTRIDE + col0 + g]);
            }
#pragma unroll
            for (int mt = 0; mt < 4; mt++)
#pragma unroll
                for (int nt = 0; nt < 4; nt++)
                    mma_tf32(acc[mt][nt][0], acc[mt][nt][1], acc[mt][nt][2], acc[mt][nt][3],
                             a[mt][0], a[mt][1], a[mt][2], a[mt][3],
                             b[nt][0], b[nt][1]);
        }
    };

    issue(0, 0);
    int buf = 0;
    for (int k0 = 16; k0 < K; k0 += 16) {
        issue(k0, buf ^ 1);
        cp_wait<1>();
        __syncthreads();
        compute(buf);
        __syncthreads();
        buf ^= 1;
    }
    cp_wait<0>();
    __syncthreads();
    compute(buf);

    // epilogue
#pragma unroll
    for (int mt = 0; mt < 4; mt++) {
#pragma unroll
        for (int nt = 0; nt < 4; nt++) {
#pragma unroll
            for (int half = 0; half < 2; half++) {
                int r = rBase + wr * 64 + mt * 16 + g + half * 8;
                int c = cBase + wc * 32 + nt * 8 + tig * 2;
                float v0 = acc[mt][nt][half * 2 + 0] + bias[c];
                float v1 = acc[mt][nt][half * 2 + 1] + bias[c + 1];
                if (MODE == 0) {
                    if (z != 0) { v0 = to_tf32(v0); v1 = to_tf32(v1); }
                    int bb = r >> 11;
                    int s  = r & 2047;
                    int h  = c >> 6;
                    int dk = c & 63;
                    size_t base = (((size_t)(bb * H_ + h) * S_) + s) * DK_ + dk;
                    C[base]     = v0;
                    C[base + 1] = v1;
                } else {
                    C[(size_t)r * N + c]     = v0;
                    C[(size_t)r * N + c + 1] = v1;
                }
            }
        }
    }
}

// ---------------------------------------------------------------------------
// Tensor-core flash attention over COMPACTED keys.
// tf32 MMA; QK^T error-compensated (Q hi/lo from fp32 g_q), K/V pre-rounded.
// K fragments via ldmatrix, V via scalar LDS (no cvt anywhere in the loop).
// cp.async double-buffered gather. Output stored tf32-rounded for out-GEMM.
// ---------------------------------------------------------------------------
#define KT 32

__global__ __launch_bounds__(128)
void attn_tc(const float* __restrict__ q, const float* __restrict__ k,
             const float* __restrict__ v, float* __restrict__ out)
{
    __shared__ __align__(16) float k_s[2][KT * 68];
    __shared__ __align__(16) float v_s[2][KT * 72];
    __shared__ float p_sm[4][16 * 36];

    const int tid  = threadIdx.x;
    const int warp = tid >> 5;
    const int lane = tid & 31;
    const int g    = lane >> 2;
    const int tig  = lane & 3;

    const int qb = blockIdx.x * 64;
    const int h  = blockIdx.y;
    const int b  = blockIdx.z;

    const int  cnt  = g_cnt[b];
    const int* idxl = g_idx + b * S_;

    const float* qbh = q + ((size_t)(b * H_ + h) * S_) * DK_;
    const float* kbh = k + ((size_t)(b * H_ + h) * S_) * DK_;
    const float* vbh = v + ((size_t)(b * H_ + h) * S_) * DV_;

    const uint32_t ksb[2] = { (uint32_t)__cvta_generic_to_shared(k_s[0]),
                              (uint32_t)__cvta_generic_to_shared(k_s[1]) };
    const uint32_t vsb[2] = { (uint32_t)__cvta_generic_to_shared(v_s[0]),
                              (uint32_t)__cvta_generic_to_shared(v_s[1]) };

    // K ldmatrix per-lane offset: n = (lane>>4)*8 + (lane&7), k = ((lane>>3)&1)*4
    const uint32_t koff = (((((lane >> 4) << 3) + (lane & 7)) * 68) + (((lane >> 3) & 1) << 2)) * 4;

    const int nTiles = (cnt + KT - 1) / KT;

    auto issue_tile = [&](int t, int buf) {
#pragma unroll
        for (int tt = 0; tt < 4; tt++) {
            int idx = tid + tt * 128;         // 0..511 chunks (16 per row)
            int row = idx >> 4;
            int c4  = (idx & 15) * 4;
            int kp  = t * KT + row;
            int kidx = (kp < cnt) ? __ldg(idxl + kp) : 0;
            cp16(ksb[buf] + (row * 68 + c4) * 4, kbh + (size_t)kidx * DK_ + c4);
            cp16(vsb[buf] + (row * 72 + c4) * 4, vbh + (size_t)kidx * DV_ + c4);
        }
        cp_commit();
    };

    issue_tile(0, 0);

    // Q fragments direct from gmem (fp32), scaled by 1/8, hi/lo split
    uint32_t qhi[8][4], qlo[8][4];
    {
        const int r0 = qb + warp * 16 + g;
        const int r1 = r0 + 8;
#pragma unroll
        for (int kt = 0; kt < 8; kt++) {
            float f0 = qbh[(size_t)r0 * DK_ + kt * 8 + tig]     * 0.125f;
            float f1 = qbh[(size_t)r1 * DK_ + kt * 8 + tig]     * 0.125f;
            float f2 = qbh[(size_t)r0 * DK_ + kt * 8 + tig + 4] * 0.125f;
            float f3 = qbh[(size_t)r1 * DK_ + kt * 8 + tig + 4] * 0.125f;
            float h0 = to_tf32(f0), h1 = to_tf32(f1), h2 = to_tf32(f2), h3 = to_tf32(f3);
            qhi[kt][0] = __float_as_uint(h0);
            qhi[kt][1] = __float_as_uint(h1);
            qhi[kt][2] = __float_as_uint(h2);
            qhi[kt][3] = __float_as_uint(h3);
            qlo[kt][0] = __float_as_uint(to_tf32(f0 - h0));
            qlo[kt][1] = __float_as_uint(to_tf32(f1 - h1));
            qlo[kt][2] = __float_as_uint(to_tf32(f2 - h2));
            qlo[kt][3] = __float_as_uint(to_tf32(f3 - h3));
        }
    }
    float* p_s = p_sm[warp];

    float m0 = -1e30f, m1 = -1e30f, l0 = 0.f, l1 = 0.f;
    float o[8][4];
#pragma unroll
    for (int nt = 0; nt < 8; nt++)
#pragma unroll
        for (int r = 0; r < 4; r++) o[nt][r] = 0.f;

    for (int t = 0; t < nTiles; t++) {
        const int kt0 = t * KT;
        if (t + 1 < nTiles) issue_tile(t + 1, (t + 1) & 1);
        else cp_commit();
        cp_wait<1>();
        __syncthreads();

        const int buf = t & 1;
        const uint32_t ksbb = ksb[buf];
        const float* vs = v_s[buf];

        // ---- QK^T : per-warp 16x32 scores (Q hi/lo compensated, K via ldmatrix) ----
        float s[4][4];
#pragma unroll
        for (int nt = 0; nt < 4; nt++)
#pragma unroll
            for (int r = 0; r < 4; r++) s[nt][r] = 0.f;

#pragma unroll
        for (int kt = 0; kt < 8; kt++) {
            uint32_t bb[4][2];
#pragma unroll
            for (int ntp = 0; ntp < 4; ntp += 2) {
                ldsm_x4(bb[ntp][0], bb[ntp][1], bb[ntp + 1][0], bb[ntp + 1][1],
                        ksbb + (uint32_t)((ntp * 8 * 68 + kt * 8) * 4) + koff);
            }
#pragma unroll
            for (int nt = 0; nt < 4; nt++) {
                mma_tf32(s[nt][0], s[nt][1], s[nt][2], s[nt][3],
                         qhi[kt][0], qhi[kt][1], qhi[kt][2], qhi[kt][3],
                         bb[nt][0], bb[nt][1]);
                mma_tf32(s[nt][0], s[nt][1], s[nt][2], s[nt][3],
                         qlo[kt][0], qlo[kt][1], qlo[kt][2], qlo[kt][3],
                         bb[nt][0], bb[nt][1]);
            }
        }

        // tail mask via select (padded rows must not win the max)
#pragma unroll
        for (int nt = 0; nt < 4; nt++) {
            int c0 = kt0 + nt * 8 + 2 * tig;
            int c1 = c0 + 1;
            if (c0 >= cnt) { s[nt][0] = -1e30f; s[nt][2] = -1e30f; }
            if (c1 >= cnt) { s[nt][1] = -1e30f; s[nt][3] = -1e30f; }
        }

        // ---- online softmax (rows g, g+8) ----
        float tm0 = -1e30f, tm1 = -1e30f;
#pragma unroll
        for (int nt = 0; nt < 4; nt++) {
            tm0 = fmaxf(tm0, fmaxf(s[nt][0], s[nt][1]));
            tm1 = fmaxf(tm1, fmaxf(s[nt][2], s[nt][3]));
        }
        tm0 = fmaxf(tm0, __shfl_xor_sync(0xffffffffu, tm0, 1));
        tm0 = fmaxf(tm0, __shfl_xor_sync(0xffffffffu, tm0, 2));
        tm1 = fmaxf(tm1, __shfl_xor_sync(0xffffffffu, tm1, 1));
        tm1 = fmaxf(tm1, __shfl_xor_sync(0xffffffffu, tm1, 2));
        float nm0 = fmaxf(m0, tm0);
        float nm1 = fmaxf(m1, tm1);
        float corr0 = __expf(m0 - nm0);
        float corr1 = __expf(m1 - nm1);
        m0 = nm0; m1 = nm1;

        float rs0 = 0.f, rs1 = 0.f;
#pragma unroll
        for (int nt = 0; nt < 4; nt++) {
            float p0 = __expf(s[nt][0] - nm0);
            float p1 = __expf(s[nt][1] - nm0);
            float p2 = __expf(s[nt][2] - nm1);
            float p3 = __expf(s[nt][3] - nm1);
            rs0 += p0 + p1;
            rs1 += p2 + p3;
            float2 w0; w0.x = to_tf32(p0); w0.y = to_tf32(p1);
            float2 w1; w1.x = to_tf32(p2); w1.y = to_tf32(p3);
            *(float2*)&p_s[g * 36 + nt * 8 + 2 * tig]       = w0;
            *(float2*)&p_s[(g + 8) * 36 + nt * 8 + 2 * tig] = w1;
        }
        rs0 += __shfl_xor_sync(0xffffffffu, rs0, 1);
        rs0 += __shfl_xor_sync(0xffffffffu, rs0, 2);
        rs1 += __shfl_xor_sync(0xffffffffu, rs1, 1);
        rs1 += __shfl_xor_sync(0xffffffffu, rs1, 2);
        l0 = l0 * corr0 + rs0;
        l1 = l1 * corr1 + rs1;

#pragma unroll
        for (int nt = 0; nt < 8; nt++) {
            o[nt][0] *= corr0; o[nt][1] *= corr0;
            o[nt][2] *= corr1; o[nt][3] *= corr1;
        }
        __syncwarp();

        // ---- PV : o(16x64) += P(16x32) @ V(32x64), V pre-rounded ----
#pragma unroll
        for (int kk = 0; kk < 4; kk++) {
            uint32_t a0 = __float_as_uint(p_s[g * 36 + kk * 8 + tig]);
            uint32_t a1 = __float_as_uint(p_s[(g + 8) * 36 + kk * 8 + tig]);
            uint32_t a2 = __float_as_uint(p_s[g * 36 + kk * 8 + tig + 4]);
            uint32_t a3 = __float_as_uint(p_s[(g + 8) * 36 + kk * 8 + tig + 4]);
#pragma unroll
            for (int nt = 0; nt < 8; nt++) {
                uint32_t bv0 = __float_as_uint(vs[(kk * 8 + tig) * 72 + nt * 8 + g]);
                uint32_t bv1 = __float_as_uint(vs[(kk * 8 + tig + 4) * 72 + nt * 8 + g]);
                mma_tf32(o[nt][0], o[nt][1], o[nt][2], o[nt][3],
                         a0, a1, a2, a3, bv0, bv1);
            }
        }
        __syncthreads();
    }

    // ---- finalize: out[b, s, h*64 + d], tf32-rounded for the out-GEMM ----
    float inv0 = 1.f / l0;
    float inv1 = 1.f / l1;
    int s0 = qb + warp * 16 + g;
    int s1 = s0 + 8;
#pragma unroll
    for (int nt = 0; nt < 8; nt++) {
        int d = nt * 8 + 2 * tig;
        float2 w0; w0.x = to_tf32(o[nt][0] * inv0); w0.y = to_tf32(o[nt][1] * inv0);
        float2 w1; w1.x = to_tf32(o[nt][2] * inv1); w1.y = to_tf32(o[nt][3] * inv1);
        *(float2*)&out[((size_t)(b * S_ + s0) * H_ + h) * DV_ + d] = w0;
        *(float2*)&out[((size_t)(b * S_ + s1) * H_ + h) * DV_ + d] = w1;
    }
}

// ---------------------------------------------------------------------------
extern "C" void kernel_launch(void* const* d_in, const int* in_sizes, int n_in,
                              void* d_out, int out_size)
{
    const float* query = (const float*)d_in[0];
    const float* key   = (const float*)d_in[1];
    const float* value = (const float*)d_in[2];
    const int*   amask = (const int*)d_in[3];
    const float* wq = (const float*)d_in[4];
    const float* bq = (const float*)d_in[5];
    const float* wk = (const float*)d_in[6];
    const float* bk = (const float*)d_in[7];
    const float* wv = (const float*)d_in[8];
    const float* bv = (const float*)d_in[9];
    const float* wo = (const float*)d_in[10];
    const float* bo = (const float*)d_in[11];
    float* out = (float*)d_out;

    float *gq, *gk, *gv, *ga, *gqc, *gkc, *gvc, *gwq, *gwk, *gwv, *gwo;
    cudaGetSymbolAddress((void**)&gq,  g_q);
    cudaGetSymbolAddress((void**)&gk,  g_k);
    cudaGetSymbolAddress((void**)&gv,  g_v);
    cudaGetSymbolAddress((void**)&ga,  g_a);
    cudaGetSymbolAddress((void**)&gqc, g_qc);
    cudaGetSymbolAddress((void**)&gkc, g_kc);
    cudaGetSymbolAddress((void**)&gvc, g_vc);
    cudaGetSymbolAddress((void**)&gwq, g_wqr);
    cudaGetSymbolAddress((void**)&gwk, g_wkr);
    cudaGetSymbolAddress((void**)&gwv, g_wvr);
    cudaGetSymbolAddress((void**)&gwo, g_wor);

    const int M = B_ * S_;       // 8192
    const int N = H_ * DK_;      // 1024
    const int K = D_;            // 1024

    compact_k<<<B_, 32>>>(amask);

    // pre-round inputs (3 big tensors) and weights (4 tensors) to tf32
    round_k<<<dim3(1024, 3), 256>>>(query, key, value, query,
                                    gqc, gkc, gvc, gqc, (B_ * S_ * D_) / 4);
    round_k<<<dim3(128, 4), 256>>>(wq, wk, wv, wo,
                                   gwq, gwk, gwv, gwo, (D_ * 1024) / 4);

    dim3 ggrid(N / 128, M / 128, 3);
    gemm_tc<0><<<ggrid, 256>>>(gqc, gkc, gvc,
                               gwq, gwk, gwv,
                               bq, bk, bv,
                               gq, gk, gv, M, N, K);

    dim3 agrid(S_ / 64, H_, B_);
    attn_tc<<<agrid, 128>>>(gq, gk, gv, ga);

    gemm_tc<1><<<dim3(1024 / 128, M / 128, 1), 256>>>(ga, ga, ga,
                                                      gwo, gwo, gwo,
                                                      bo, bo, bo,
                                                      out, out, out, M, 1024, H_ * DV_);
}

// round 11
// speedup vs baseline: 4.6127x; 1.0252x over previous
#include <cuda_runtime.h>
#include <math.h>
#include <stdint.h>

#define B_  4
#define S_  2048
#define D_  1024
#define H_  16
#define DK_ 64
#define DV_ 64

// Scratch (alloc-free rule: __device__ globals)
__device__ float g_q[B_*H_*S_*DK_];   // [B,H,S,DK] fp32 (raw)
__device__ float g_k[B_*H_*S_*DK_];   // [B,H,S,DK] tf32-rounded
__device__ float g_v[B_*H_*S_*DV_];   // [B,H,S,DV] tf32-rounded
__device__ float g_a[B_*S_*H_*DV_];   // [B,S,H*DV] tf32-rounded
__device__ float g_qc[B_*S_*D_];      // rounded copy of query
__device__ float g_kc[B_*S_*D_];      // rounded copy of key
__device__ float g_vc[B_*S_*D_];      // rounded copy of value
__device__ float g_wqr[D_*H_*DK_];
__device__ float g_wkr[D_*H_*DK_];
__device__ float g_wvr[D_*H_*DV_];
__device__ float g_wor[H_*DV_*D_];
__device__ int   g_idx[B_*S_];        // compacted unmasked key indices
__device__ int   g_cnt[B_];           // count per batch

__device__ __forceinline__ float to_tf32(float x) {
    float r;
    asm("cvt.rna.tf32.f32 %0, %1;" : "=f"(r) : "f"(x));
    return r;
}

__device__ __forceinline__ void mma_tf32(float& d0, float& d1, float& d2, float& d3,
                                         uint32_t a0, uint32_t a1, uint32_t a2, uint32_t a3,
                                         uint32_t b0, uint32_t b1)
{
    asm volatile(
        "mma.sync.aligned.m16n8k8.row.col.f32.tf32.tf32.f32 "
        "{%0,%1,%2,%3}, {%4,%5,%6,%7}, {%8,%9}, {%0,%1,%2,%3};"
        : "+f"(d0), "+f"(d1), "+f"(d2), "+f"(d3)
        : "r"(a0), "r"(a1), "r"(a2), "r"(a3), "r"(b0), "r"(b1));
}

__device__ __forceinline__ void ldsm_x4(uint32_t& r0, uint32_t& r1, uint32_t& r2, uint32_t& r3,
                                        uint32_t addr)
{
    asm volatile("ldmatrix.sync.aligned.m8n8.x4.shared.b16 {%0,%1,%2,%3}, [%4];"
                 : "=r"(r0), "=r"(r1), "=r"(r2), "=r"(r3) : "r"(addr));
}

__device__ __forceinline__ void cp16(uint32_t dst_smem, const void* src) {
    asm volatile("cp.async.cg.shared.global [%0], [%1], 16;" :: "r"(dst_smem), "l"(src));
}
__device__ __forceinline__ void cp_commit() {
    asm volatile("cp.async.commit_group;");
}
template<int N>
__device__ __forceinline__ void cp_wait() {
    asm volatile("cp.async.wait_group %0;" :: "n"(N));
}

// ---------------------------------------------------------------------------
// Mask compaction: one warp per batch. Keys with mask==0 survive.
// ---------------------------------------------------------------------------
__global__ void compact_k(const int* __restrict__ mask)
{
    const int b = blockIdx.x;
    const int lane = threadIdx.x;
    int c = 0;
    for (int base = 0; base < S_; base += 32) {
        int mv = mask[b * S_ + base + lane];
        unsigned ball = __ballot_sync(0xffffffffu, mv == 0);
        int rank = __popc(ball & ((1u << lane) - 1));
        if (mv == 0) g_idx[b * S_ + c + rank] = base + lane;
        c += __popc(ball);
    }
    if (lane == 0) g_cnt[b] = c;
}

// ---------------------------------------------------------------------------
// Pre-round to tf32 (rna), vectorized. blockIdx.y selects the tensor.
// ---------------------------------------------------------------------------
__global__ void round_k(const float* __restrict__ s0, const float* __restrict__ s1,
                        const float* __restrict__ s2, const float* __restrict__ s3,
                        float* __restrict__ d0, float* __restrict__ d1,
                        float* __restrict__ d2, float* __restrict__ d3, int n4)
{
    const int z = blockIdx.y;
    const float* s = (z == 0) ? s0 : (z == 1) ? s1 : (z == 2) ? s2 : s3;
    float*       d = (z == 0) ? d0 : (z == 1) ? d1 : (z == 2) ? d2 : d3;
    const int stride = gridDim.x * blockDim.x;
    for (int i = blockIdx.x * blockDim.x + threadIdx.x; i < n4; i += stride) {
        float4 v = ((const float4*)s)[i];
        v.x = to_tf32(v.x); v.y = to_tf32(v.y);
        v.z = to_tf32(v.z); v.w = to_tf32(v.w);
        ((float4*)d)[i] = v;
    }
}

// ---------------------------------------------------------------------------
// tf32 tensor-core GEMM. Inputs PRE-ROUNDED to tf32 -> no cvt anywhere.
// 3-stage cp.async pipeline, ONE __syncthreads per k-iter.
// XOR-swizzled smem (no padding): A [row][16] chunk^=swz(r), B [k][128]
// chunk^=swz(k)<<1. 3 x 16KB = 48KB static smem.
// Block tile 128x128, k-step 16, 256 threads = 8 warps (2x4), warp tile 64x32.
// MODE 0: fused QKV (z selects set), scatter-store [B,H,S,64];
//         z=1,2 (K,V) stored tf32-rounded, z=0 (Q) raw fp32.
// MODE 1: single GEMM, row-major store.
// ---------------------------------------------------------------------------
template<int MODE>
__global__ __launch_bounds__(256)
void gemm_tc(const float* __restrict__ A0, const float* __restrict__ A1,
             const float* __restrict__ A2,
             const float* __restrict__ W0, const float* __restrict__ W1,
             const float* __restrict__ W2,
             const float* __restrict__ b0p, const float* __restrict__ b1p,
             const float* __restrict__ b2p,
             float* __restrict__ C0, float* __restrict__ C1, float* __restrict__ C2,
             int M, int N, int K)
{
    __shared__ __align__(16) float As[3][128 * 16];
    __shared__ __align__(16) float Bs[3][16 * 128];

    const int z = (MODE == 0) ? blockIdx.z : 0;
    const float* A    = (z == 0) ? A0 : (z == 1) ? A1 : A2;
    const float* W    = (z == 0) ? W0 : (z == 1) ? W1 : W2;
    const float* bias = (z == 0) ? b0p : (z == 1) ? b1p : b2p;
    float*       C    = (z == 0) ? C0 : (z == 1) ? C1 : C2;

    const int tid  = threadIdx.x;
    const int warp = tid >> 5;
    const int lane = tid & 31;
    const int g    = lane >> 2;
    const int tig  = lane & 3;
    const int wr   = warp >> 2;
    const int wc   = warp & 3;

    const int rBase = blockIdx.y * 128;
    const int cBase = blockIdx.x * 128;

    const uint32_t asb[3] = { (uint32_t)__cvta_generic_to_shared(As[0]),
                              (uint32_t)__cvta_generic_to_shared(As[1]),
                              (uint32_t)__cvta_generic_to_shared(As[2]) };
    const uint32_t bsb[3] = { (uint32_t)__cvta_generic_to_shared(Bs[0]),
                              (uint32_t)__cvta_generic_to_shared(Bs[1]),
                              (uint32_t)__cvta_generic_to_shared(Bs[2]) };

    // ldmatrix per-lane: m within 16-row tile, khalf selects k 0-3 / 4-7
    const int m16   = lane & 15;
    const int khalf = lane >> 4;
    const int swzm  = (m16 + (m16 >> 2)) & 3;

    auto issue = [&](int k0, int buf) {
#pragma unroll
        for (int j = 0; j < 2; j++) {
            int idx = tid + j * 256;          // A: 512 chunks of 16B
            int r   = idx >> 2;
            int qq  = idx & 3;
            int swr = (r + (r >> 2)) & 3;
            cp16(asb[buf] + ((r * 16 + ((qq ^ swr) << 2)) << 2),
                 A + (size_t)(rBase + r) * K + k0 + qq * 4);
        }
#pragma unroll
        for (int j = 0; j < 2; j++) {
            int idx = tid + j * 256;          // B: 512 chunks
            int kr  = idx >> 5;
            int cc  = idx & 31;
            int swk = ((kr + (kr >> 2)) & 3) << 1;
            cp16(bsb[buf] + ((kr * 128 + ((cc ^ swk) << 2)) << 2),
                 W + (size_t)(k0 + kr) * N + cBase + cc * 4);
        }
        cp_commit();
    };

    float acc[4][4][4];
#pragma unroll
    for (int mt = 0; mt < 4; mt++)
#pragma unroll
        for (int nt = 0; nt < 4; nt++)
#pragma unroll
            for (int r = 0; r < 4; r++) acc[mt][nt][r] = 0.f;

    auto compute = [&](int buf) {
        const uint32_t as = asb[buf];
        const float* bs = Bs[buf];
#pragma unroll
        for (int ks = 0; ks < 2; ks++) {
            const int kb = ks * 8;
            uint32_t a[4][4];
#pragma unroll
            for (int mt = 0; mt < 4; mt++) {
                int row0 = wr * 64 + mt * 16;
                uint32_t addr = as +
                    (uint32_t)(((row0 + m16) * 16 + (((2 * ks + khalf) ^ swzm) << 2)) << 2);
                ldsm_x4(a[mt][0], a[mt][1], a[mt][2], a[mt][3], addr);
            }
            int kr0 = kb + tig, kr1 = kb + tig + 4;
            int sw0 = ((kr0 + (kr0 >> 2)) & 3) << 1;
            int sw1 = ((kr1 + (kr1 >> 2)) & 3) << 1;
            uint32_t b[4][2];
#pragma unroll
            for (int nt = 0; nt < 4; nt++) {
                int col = wc * 32 + nt * 8 + g;
                int chi = col >> 2, clo = col & 3;
                b[nt][0] = __float_as_uint(bs[kr0 * 128 + ((chi ^ sw0) << 2) + clo]);
                b[nt][1] = __float_as_uint(bs[kr1 * 128 + ((chi ^ sw1) << 2) + clo]);
            }
#pragma unroll
            for (int mt = 0; mt < 4; mt++)
#pragma unroll
                for (int nt = 0; nt < 4; nt++)
                    mma_tf32(acc[mt][nt][0], acc[mt][nt][1], acc[mt][nt][2], acc[mt][nt][3],
                             a[mt][0], a[mt][1], a[mt][2], a[mt][3],
                             b[nt][0], b[nt][1]);
        }
    };

    const int niter = K / 16;
    issue(0, 0);
    issue(16, 1);
    for (int i = 0; i < niter; i++) {
        cp_wait<1>();
        __syncthreads();
        compute(i % 3);
        if (i + 2 < niter) issue((i + 2) * 16, (i + 2) % 3);
        else cp_commit();
    }

    // epilogue
#pragma unroll
    for (int mt = 0; mt < 4; mt++) {
#pragma unroll
        for (int nt = 0; nt < 4; nt++) {
#pragma unroll
            for (int half = 0; half < 2; half++) {
                int r = rBase + wr * 64 + mt * 16 + g + half * 8;
                int c = cBase + wc * 32 + nt * 8 + tig * 2;
                float v0 = acc[mt][nt][half * 2 + 0] + bias[c];
                float v1 = acc[mt][nt][half * 2 + 1] + bias[c + 1];
                if (MODE == 0) {
                    if (z != 0) { v0 = to_tf32(v0); v1 = to_tf32(v1); }
                    int bb = r >> 11;
                    int s  = r & 2047;
                    int h  = c >> 6;
                    int dk = c & 63;
                    size_t base = (((size_t)(bb * H_ + h) * S_) + s) * DK_ + dk;
                    C[base]     = v0;
                    C[base + 1] = v1;
                } else {
                    C[(size_t)r * N + c]     = v0;
                    C[(size_t)r * N + c + 1] = v1;
                }
            }
        }
    }
}

// ---------------------------------------------------------------------------
// Tensor-core flash attention over COMPACTED keys.
// 256 threads / 8 warps, 128 q-rows per block (16 per warp) -> K/V smem and
// gather traffic amortized over 2x compute; 8 resident warps/SM.
// tf32 MMA; QK^T error-compensated (Q hi/lo), K/V pre-rounded, K via ldmatrix.
// P (C-layout) converted to A-layout fragments by warp shuffles -- no P smem.
// cp.async double-buffered K/V gather.
// ---------------------------------------------------------------------------
#define KT 32

__global__ __launch_bounds__(256)
void attn_tc(const float* __restrict__ q, const float* __restrict__ k,
             const float* __restrict__ v, float* __restrict__ out)
{
    __shared__ __align__(16) float k_s[2][KT * 68];
    __shared__ __align__(16) float v_s[2][KT * 72];

    const int tid  = threadIdx.x;
    const int warp = tid >> 5;
    const int lane = tid & 31;
    const int g    = lane >> 2;
    const int tig  = lane & 3;

    const int qb = blockIdx.x * 128;
    const int h  = blockIdx.y;
    const int b  = blockIdx.z;

    const int  cnt  = g_cnt[b];
    const int* idxl = g_idx + b * S_;

    const float* qbh = q + ((size_t)(b * H_ + h) * S_) * DK_;
    const float* kbh = k + ((size_t)(b * H_ + h) * S_) * DK_;
    const float* vbh = v + ((size_t)(b * H_ + h) * S_) * DV_;

    const uint32_t ksb[2] = { (uint32_t)__cvta_generic_to_shared(k_s[0]),
                              (uint32_t)__cvta_generic_to_shared(k_s[1]) };
    const uint32_t vsb[2] = { (uint32_t)__cvta_generic_to_shared(v_s[0]),
                              (uint32_t)__cvta_generic_to_shared(v_s[1]) };

    // K ldmatrix per-lane offset: n = (lane>>4)*8 + (lane&7), k = ((lane>>3)&1)*4
    const uint32_t koff = (((((lane >> 4) << 3) + (lane & 7)) * 68) + (((lane >> 3) & 1) << 2)) * 4;

    // P shuffle sources: col tig held by lane 4g+(tig>>1); col tig+4 by +2
    const int psrc0 = (lane & ~3) | (tig >> 1);
    const int psrc1 = psrc0 + 2;
    const bool podd = (tig & 1);

    const int nTiles = (cnt + KT - 1) / KT;

    auto issue_tile = [&](int t, int buf) {
#pragma unroll
        for (int tt = 0; tt < 2; tt++) {
            int idx = tid + tt * 256;         // 0..511 chunks (16 per row)
            int row = idx >> 4;
            int c4  = (idx & 15) * 4;
            int kp  = t * KT + row;
            int kidx = (kp < cnt) ? __ldg(idxl + kp) : 0;
            cp16(ksb[buf] + (row * 68 + c4) * 4, kbh + (size_t)kidx * DK_ + c4);
            cp16(vsb[buf] + (row * 72 + c4) * 4, vbh + (size_t)kidx * DV_ + c4);
        }
        cp_commit();
    };

    issue_tile(0, 0);

    // Q fragments direct from gmem (fp32), scaled by 1/8, hi/lo split
    uint32_t qhi[8][4], qlo[8][4];
    {
        const int r0 = qb + warp * 16 + g;
        const int r1 = r0 + 8;
#pragma unroll
        for (int kt = 0; kt < 8; kt++) {
            float f0 = qbh[(size_t)r0 * DK_ + kt * 8 + tig]     * 0.125f;
            float f1 = qbh[(size_t)r1 * DK_ + kt * 8 + tig]     * 0.125f;
            float f2 = qbh[(size_t)r0 * DK_ + kt * 8 + tig + 4] * 0.125f;
            float f3 = qbh[(size_t)r1 * DK_ + kt * 8 + tig + 4] * 0.125f;
            float h0 = to_tf32(f0), h1 = to_tf32(f1), h2 = to_tf32(f2), h3 = to_tf32(f3);
            qhi[kt][0] = __float_as_uint(h0);
            qhi[kt][1] = __float_as_uint(h1);
            qhi[kt][2] = __float_as_uint(h2);
            qhi[kt][3] = __float_as_uint(h3);
            qlo[kt][0] = __float_as_uint(to_tf32(f0 - h0));
            qlo[kt][1] = __float_as_uint(to_tf32(f1 - h1));
            qlo[kt][2] = __float_as_uint(to_tf32(f2 - h2));
            qlo[kt][3] = __float_as_uint(to_tf32(f3 - h3));
        }
    }

    float m0 = -1e30f, m1 = -1e30f, l0 = 0.f, l1 = 0.f;
    float o[8][4];
#pragma unroll
    for (int nt = 0; nt < 8; nt++)
#pragma unroll
        for (int r = 0; r < 4; r++) o[nt][r] = 0.f;

    for (int t = 0; t < nTiles; t++) {
        const int kt0 = t * KT;
        if (t + 1 < nTiles) issue_tile(t + 1, (t + 1) & 1);
        else cp_commit();
        cp_wait<1>();
        __syncthreads();

        const int buf = t & 1;
        const uint32_t ksbb = ksb[buf];
        const float* vs = v_s[buf];

        // ---- QK^T : per-warp 16x32 scores (Q hi/lo compensated, K via ldmatrix) ----
        float s[4][4];
#pragma unroll
        for (int nt = 0; nt < 4; nt++)
#pragma unroll
            for (int r = 0; r < 4; r++) s[nt][r] = 0.f;

#pragma unroll
        for (int kt = 0; kt < 8; kt++) {
            uint32_t bb[4][2];
#pragma unroll
            for (int ntp = 0; ntp < 4; ntp += 2) {
                ldsm_x4(bb[ntp][0], bb[ntp][1], bb[ntp + 1][0], bb[ntp + 1][1],
                        ksbb + (uint32_t)((ntp * 8 * 68 + kt * 8) * 4) + koff);
            }
#pragma unroll
            for (int nt = 0; nt < 4; nt++) {
                mma_tf32(s[nt][0], s[nt][1], s[nt][2], s[nt][3],
                         qhi[kt][0], qhi[kt][1], qhi[kt][2], qhi[kt][3],
                         bb[nt][0], bb[nt][1]);
                mma_tf32(s[nt][0], s[nt][1], s[nt][2], s[nt][3],
                         qlo[kt][0], qlo[kt][1], qlo[kt][2], qlo[kt][3],
                         bb[nt][0], bb[nt][1]);
            }
        }

        // tail mask via select (padded rows must not win the max)
#pragma unroll
        for (int nt = 0; nt < 4; nt++) {
            int c0 = kt0 + nt * 8 + 2 * tig;
            int c1 = c0 + 1;
            if (c0 >= cnt) { s[nt][0] = -1e30f; s[nt][2] = -1e30f; }
            if (c1 >= cnt) { s[nt][1] = -1e30f; s[nt][3] = -1e30f; }
        }

        // ---- online softmax (rows g, g+8) ----
        float tm0 = -1e30f, tm1 = -1e30f;
#pragma unroll
        for (int nt = 0; nt < 4; nt++) {
            tm0 = fmaxf(tm0, fmaxf(s[nt][0], s[nt][1]));
            tm1 = fmaxf(tm1, fmaxf(s[nt][2], s[nt][3]));
        }
        tm0 = fmaxf(tm0, __shfl_xor_sync(0xffffffffu, tm0, 1));
        tm0 = fmaxf(tm0, __shfl_xor_sync(0xffffffffu, tm0, 2));
        tm1 = fmaxf(tm1, __shfl_xor_sync(0xffffffffu, tm1, 1));
        tm1 = fmaxf(tm1, __shfl_xor_sync(0xffffffffu, tm1, 2));
        float nm0 = fmaxf(m0, tm0);
        float nm1 = fmaxf(m1, tm1);
        float corr0 = __expf(m0 - nm0);
        float corr1 = __expf(m1 - nm1);
        m0 = nm0; m1 = nm1;

        float pr[4][4];
        float rs0 = 0.f, rs1 = 0.f;
#pragma unroll
        for (int nt = 0; nt < 4; nt++) {
            float p0 = __expf(s[nt][0] - nm0);
            float p1 = __expf(s[nt][1] - nm0);
            float p2 = __expf(s[nt][2] - nm1);
            float p3 = __expf(s[nt][3] - nm1);
            rs0 += p0 + p1;
            rs1 += p2 + p3;
            pr[nt][0] = to_tf32(p0);
            pr[nt][1] = to_tf32(p1);
            pr[nt][2] = to_tf32(p2);
            pr[nt][3] = to_tf32(p3);
        }
        rs0 += __shfl_xor_sync(0xffffffffu, rs0, 1);
        rs0 += __shfl_xor_sync(0xffffffffu, rs0, 2);
        rs1 += __shfl_xor_sync(0xffffffffu, rs1, 1);
        rs1 += __shfl_xor_sync(0xffffffffu, rs1, 2);
        l0 = l0 * corr0 + rs0;
        l1 = l1 * corr1 + rs1;

#pragma unroll
        for (int nt = 0; nt < 8; nt++) {
            o[nt][0] *= corr0; o[nt][1] *= corr0;
            o[nt][2] *= corr1; o[nt][3] *= corr1;
        }

        // ---- PV : o(16x64) += P(16x32) @ V(32x64) ----
        // A-frags of P built by warp shuffles from the C-layout registers.
#pragma unroll
        for (int kk = 0; kk < 4; kk++) {
            float x0 = __shfl_sync(0xffffffffu, pr[kk][0], psrc0);
            float x1 = __shfl_sync(0xffffffffu, pr[kk][1], psrc0);
            float x2 = __shfl_sync(0xffffffffu, pr[kk][2], psrc0);
            float x3 = __shfl_sync(0xffffffffu, pr[kk][3], psrc0);
            float y0 = __shfl_sync(0xffffffffu, pr[kk][0], psrc1);
            float y1 = __shfl_sync(0xffffffffu, pr[kk][1], psrc1);
            float y2 = __shfl_sync(0xffffffffu, pr[kk][2], psrc1);
            float y3 = __shfl_sync(0xffffffffu, pr[kk][3], psrc1);
            uint32_t a0 = __float_as_uint(podd ? x1 : x0);   // P[g,    kk*8+tig]
            uint32_t a1 = __float_as_uint(podd ? x3 : x2);   // P[g+8,  kk*8+tig]
            uint32_t a2 = __float_as_uint(podd ? y1 : y0);   // P[g,    kk*8+tig+4]
            uint32_t a3 = __float_as_uint(podd ? y3 : y2);   // P[g+8,  kk*8+tig+4]
#pragma unroll
            for (int nt = 0; nt < 8; nt++) {
                uint32_t bv0 = __float_as_uint(vs[(kk * 8 + tig) * 72 + nt * 8 + g]);
                uint32_t bv1 = __float_as_uint(vs[(kk * 8 + tig + 4) * 72 + nt * 8 + g]);
                mma_tf32(o[nt][0], o[nt][1], o[nt][2], o[nt][3],
                         a0, a1, a2, a3, bv0, bv1);
            }
        }
        __syncthreads();
    }

    // ---- finalize: out[b, s, h*64 + d], tf32-rounded for the out-GEMM ----
    float inv0 = 1.f / l0;
    float inv1 = 1.f / l1;
    int s0 = qb + warp * 16 + g;
    int s1 = s0 + 8;
#pragma unroll
    for (int nt = 0; nt < 8; nt++) {
        int d = nt * 8 + 2 * tig;
        float2 w0; w0.x = to_tf32(o[nt][0] * inv0); w0.y = to_tf32(o[nt][1] * inv0);
        float2 w1; w1.x = to_tf32(o[nt][2] * inv1); w1.y = to_tf32(o[nt][3] * inv1);
        *(float2*)&out[((size_t)(b * S_ + s0) * H_ + h) * DV_ + d] = w0;
        *(float2*)&out[((size_t)(b * S_ + s1) * H_ + h) * DV_ + d] = w1;
    }
}

// ---------------------------------------------------------------------------
extern "C" void kernel_launch(void* const* d_in, const int* in_sizes, int n_in,
                              void* d_out, int out_size)
{
    const float* query = (const float*)d_in[0];
    const float* key   = (const float*)d_in[1];
    const float* value = (const float*)d_in[2];
    const int*   amask = (const int*)d_in[3];
    const float* wq = (const float*)d_in[4];
    const float* bq = (const float*)d_in[5];
    const float* wk = (const float*)d_in[6];
    const float* bk = (const float*)d_in[7];
    const float* wv = (const float*)d_in[8];
    const float* bv = (const float*)d_in[9];
    const float* wo = (const float*)d_in[10];
    const float* bo = (const float*)d_in[11];
    float* out = (float*)d_out;

    float *gq, *gk, *gv, *ga, *gqc, *gkc, *gvc, *gwq, *gwk, *gwv, *gwo;
    cudaGetSymbolAddress((void**)&gq,  g_q);
    cudaGetSymbolAddress((void**)&gk,  g_k);
    cudaGetSymbolAddress((void**)&gv,  g_v);
    cudaGetSymbolAddress((void**)&ga,  g_a);
    cudaGetSymbolAddress((void**)&gqc, g_qc);
    cudaGetSymbolAddress((void**)&gkc, g_kc);
    cudaGetSymbolAddress((void**)&gvc, g_vc);
    cudaGetSymbolAddress((void**)&gwq, g_wqr);
    cudaGetSymbolAddress((void**)&gwk, g_wkr);
    cudaGetSymbolAddress((void**)&gwv, g_wvr);
    cudaGetSymbolAddress((void**)&gwo, g_wor);

    const int M = B_ * S_;       // 8192
    const int N = H_ * DK_;      // 1024
    const int K = D_;            // 1024

    compact_k<<<B_, 32>>>(amask);

    // pre-round inputs (3 big tensors) and weights (4 tensors) to tf32
    round_k<<<dim3(1024, 3), 256>>>(query, key, value, query,
                                    gqc, gkc, gvc, gqc, (B_ * S_ * D_) / 4);
    round_k<<<dim3(128, 4), 256>>>(wq, wk, wv, wo,
                                   gwq, gwk, gwv, gwo, (D_ * 1024) / 4);

    dim3 ggrid(N / 128, M / 128, 3);
    gemm_tc<0><<<ggrid, 256>>>(gqc, gkc, gvc,
                               gwq, gwk, gwv,
                               bq, bk, bv,
                               gq, gk, gv, M, N, K);

    dim3 agrid(S_ / 128, H_, B_);
    attn_tc<<<agrid, 256>>>(gq, gk, gv, ga);

    gemm_tc<1><<<dim3(1024 / 128, M / 128, 1), 256>>>(ga, ga, ga,
                                                      gwo, gwo, gwo,
                                                      bo, bo, bo,
                                                      out, out, out, M, 1024, H_ * DV_);
}